// round 1
// baseline (speedup 1.0000x reference)
#include <cuda_runtime.h>

#define D 128
#define NV 11   // 1 primal + 4 first-order + 6 second-order vectors

__global__ __launch_bounds__(128, 6)
void pinn_kernel(const float* __restrict__ x, const float* __restrict__ y,
                 const float* __restrict__ z, const float* __restrict__ t,
                 const float* __restrict__ W0, const float* __restrict__ b0,
                 const float* __restrict__ Wh, const float* __restrict__ bh,
                 const float* __restrict__ Wout, const float* __restrict__ bout,
                 const float* __restrict__ act_coeff,
                 float* __restrict__ out, int N)
{
    __shared__ __align__(16) float cur[2][NV][D];
    __shared__ float red[48];

    const int n = blockIdx.x;
    const int j = threadIdx.x;
    const float ac = act_coeff[0];

    // Pair order: xx yy zz xy xz yz
    const int PI[6] = {0, 1, 2, 0, 0, 1};
    const int PJ[6] = {0, 1, 2, 1, 2, 2};

    // Input transform: X = 2*(p-LB)/(UB-LB) - 1
    // x,y,z: LB=-1,UB=1 -> X=p (dX/dp=1).  t: LB=0,UB=1 -> X=2t-1 (dX/dt=2).
    const float X0 = x[n];
    const float X1 = y[n];
    const float X2 = z[n];
    const float X3 = 2.0f * t[n] - 1.0f;

    // ---------- Layer 0 (4 -> 128) ----------
    {
        float w0j = __ldg(&W0[0 * D + j]);
        float w1j = __ldg(&W0[1 * D + j]);
        float w2j = __ldg(&W0[2 * D + j]);
        float w3j = __ldg(&W0[3 * D + j]);
        float zz = ac * (X0 * w0j + X1 * w1j + X2 * w2j + X3 * w3j + __ldg(&b0[j]));
        float a  = tanhf(zz);
        float t1 = 1.0f - a * a;
        float dz[4];
        dz[0] = ac * w0j;
        dz[1] = ac * w1j;
        dz[2] = ac * w2j;
        dz[3] = ac * 2.0f * w3j;
        cur[0][0][j] = a;
        #pragma unroll
        for (int i = 0; i < 4; i++) cur[0][1 + i][j] = t1 * dz[i];
        #pragma unroll
        for (int p = 0; p < 6; p++)
            cur[0][5 + p][j] = -2.0f * a * t1 * dz[PI[p]] * dz[PJ[p]];
    }
    __syncthreads();

    // ---------- 5 hidden layers (128 -> 128) ----------
    int buf = 0;
    for (int l = 0; l < 5; l++) {
        const float* __restrict__ W  = Wh + l * D * D;
        const float* __restrict__ bl = bh + l * D;

        float acc[NV];
        #pragma unroll
        for (int v = 0; v < NV; v++) acc[v] = 0.0f;

        #pragma unroll 4
        for (int k4 = 0; k4 < D / 4; k4++) {
            const float wa = __ldg(&W[(4 * k4 + 0) * D + j]);
            const float wb = __ldg(&W[(4 * k4 + 1) * D + j]);
            const float wc = __ldg(&W[(4 * k4 + 2) * D + j]);
            const float wd = __ldg(&W[(4 * k4 + 3) * D + j]);
            #pragma unroll
            for (int v = 0; v < NV; v++) {
                const float4 h4 = *reinterpret_cast<const float4*>(&cur[buf][v][4 * k4]);
                acc[v] = fmaf(wa, h4.x, acc[v]);
                acc[v] = fmaf(wb, h4.y, acc[v]);
                acc[v] = fmaf(wc, h4.z, acc[v]);
                acc[v] = fmaf(wd, h4.w, acc[v]);
            }
        }

        const int nb = buf ^ 1;
        const float zz = ac * (acc[0] + __ldg(&bl[j]));
        const float a  = tanhf(zz);
        const float t1 = 1.0f - a * a;
        float ndz[4];
        #pragma unroll
        for (int i = 0; i < 4; i++) ndz[i] = ac * acc[1 + i];
        cur[nb][0][j] = a;
        #pragma unroll
        for (int i = 0; i < 4; i++) cur[nb][1 + i][j] = t1 * ndz[i];
        #pragma unroll
        for (int p = 0; p < 6; p++) {
            const float d2z = ac * acc[5 + p];
            cur[nb][5 + p][j] = t1 * (d2z - 2.0f * a * ndz[PI[p]] * ndz[PJ[p]]);
        }
        buf = nb;
        __syncthreads();
    }

    // ---------- Output layer (128 -> 4): 44 dot products ----------
    // combo c = v*4 + o : red[c] = sum_k cur[v][k] * Wout[k*4+o]
    {
        const int wid  = j >> 5;
        const int lane = j & 31;
        for (int c = wid; c < 44; c += 4) {
            const int v = c >> 2;
            const int o = c & 3;
            float s = 0.0f;
            #pragma unroll
            for (int k = lane; k < D; k += 32)
                s = fmaf(cur[buf][v][k], __ldg(&Wout[k * 4 + o]), s);
            #pragma unroll
            for (int off = 16; off > 0; off >>= 1)
                s += __shfl_xor_sync(0xffffffffu, s, off);
            if (lane == 0) red[c] = s;
        }
    }
    __syncthreads();

    if (j == 0) {
        float Y[4], Jm[4][4], H[3][6];
        #pragma unroll
        for (int o = 0; o < 4; o++) Y[o] = red[o] + __ldg(&bout[o]);
        #pragma unroll
        for (int i = 0; i < 4; i++)
            #pragma unroll
            for (int o = 0; o < 4; o++) Jm[o][i] = red[(1 + i) * 4 + o];
        #pragma unroll
        for (int p = 0; p < 6; p++)
            #pragma unroll
            for (int o = 0; o < 3; o++) H[o][p] = red[(5 + p) * 4 + o];

        const float u = Y[0], v = Y[1], w = Y[2];
        const float u_x = Jm[0][0], u_y = Jm[0][1], u_z = Jm[0][2], u_t = Jm[0][3];
        const float v_x = Jm[1][0], v_y = Jm[1][1], v_z = Jm[1][2], v_t = Jm[1][3];
        const float w_x = Jm[2][0], w_y = Jm[2][1], w_z = Jm[2][2], w_t = Jm[2][3];
        const float p_x = Jm[3][0], p_y = Jm[3][1], p_z = Jm[3][2];

        // pair idx: 0=xx 1=yy 2=zz 3=xy 4=xz 5=yz
        const float tau_x = 2.0f * H[0][0] + H[0][1] + H[1][3] + H[0][2] + H[2][4];
        const float tau_y = H[0][3] + H[1][0] + 2.0f * H[1][1] + H[1][2] + H[2][5];
        const float tau_z = H[0][4] + H[2][0] + H[1][5] + H[2][1] + 2.0f * H[2][2];

        out[0 * N + n] = u_x + v_y + w_z;
        out[1 * N + n] = u_t + (u * u_x + v * u_y + w * u_z) + p_x - tau_x;
        out[2 * N + n] = v_t + (u * v_x + v * v_y + w * v_z) + p_y - tau_y;
        out[3 * N + n] = w_t + (u * w_x + v * w_y + w * w_z) + p_z - tau_z + 98.9f;
    }
}

extern "C" void kernel_launch(void* const* d_in, const int* in_sizes, int n_in,
                              void* d_out, int out_size)
{
    const float* x    = (const float*)d_in[0];
    const float* y    = (const float*)d_in[1];
    const float* z    = (const float*)d_in[2];
    const float* t    = (const float*)d_in[3];
    const float* W0   = (const float*)d_in[4];
    const float* b0   = (const float*)d_in[5];
    const float* Wh   = (const float*)d_in[6];
    const float* bh   = (const float*)d_in[7];
    const float* Wout = (const float*)d_in[8];
    const float* bout = (const float*)d_in[9];
    const float* ac   = (const float*)d_in[10];

    const int N = in_sizes[0];
    pinn_kernel<<<N, 128>>>(x, y, z, t, W0, b0, Wh, bh, Wout, bout, ac,
                            (float*)d_out, N);
}

// round 3
// speedup vs baseline: 1.5798x; 1.5798x over previous
#include <cuda_runtime.h>

#define D 128
#define NP 6   // 11 state vectors packed as 6 float2 pairs (12th slot = 0)

__device__ __forceinline__ float2 ffma2(float2 a, float2 b, float2 c) {
    float2 d;
    asm("fma.rn.f32x2 %0, %1, %2, %3;"
        : "=l"(reinterpret_cast<unsigned long long&>(d))
        : "l"(reinterpret_cast<unsigned long long&>(a)),
          "l"(reinterpret_cast<unsigned long long&>(b)),
          "l"(reinterpret_cast<unsigned long long&>(c)));
    return d;
}

// vector order: v0 primal | v1..v4 d/d{x,y,z,t} | v5..v10 second order xx,yy,zz,xy,xz,yz
// pair layout: p0=(v0,v1) p1=(v2,v3) p2=(v4,v5) p3=(v6,v7) p4=(v8,v9) p5=(v10,0)

__global__ __launch_bounds__(128, 4)
void pinn_kernel(const float* __restrict__ x, const float* __restrict__ y,
                 const float* __restrict__ z, const float* __restrict__ t,
                 const float* __restrict__ W0, const float* __restrict__ b0,
                 const float* __restrict__ Wh, const float* __restrict__ bh,
                 const float* __restrict__ Wout, const float* __restrict__ bout,
                 const float* __restrict__ act_coeff,
                 float* __restrict__ out, int N)
{
    __shared__ __align__(16) float2 shp[4][NP][D];
    __shared__ float red[4][48];

    const int pt_l = threadIdx.x >> 5;          // warp == point
    const int lane = threadIdx.x & 31;
    const int n    = blockIdx.x * 4 + pt_l;
    if (n >= N) return;
    const float ac = act_coeff[0];

    float2 (* __restrict__ sh)[D] = shp[pt_l];

    const int PI[6] = {0, 1, 2, 0, 0, 1};
    const int PJ[6] = {0, 1, 2, 1, 2, 2};

    // Input transform: x,y,z pass through; t -> 2t-1 (dX/dt = 2).
    const float X0 = x[n];
    const float X1 = y[n];
    const float X2 = z[n];
    const float X3 = 2.0f * t[n] - 1.0f;

    // ---------------- Layer 0 (4 -> 128), 4 columns per thread ----------------
    #pragma unroll
    for (int q = 0; q < 4; q++) {
        const int c = lane + 32 * q;
        const float w0j = W0[0 * D + c];
        const float w1j = W0[1 * D + c];
        const float w2j = W0[2 * D + c];
        const float w3j = W0[3 * D + c];
        const float zz = ac * (X0 * w0j + X1 * w1j + X2 * w2j + X3 * w3j + b0[c]);
        const float a  = tanhf(zz);
        const float t1 = 1.0f - a * a;
        float dz[4];
        dz[0] = ac * w0j; dz[1] = ac * w1j; dz[2] = ac * w2j; dz[3] = ac * 2.0f * w3j;
        float nv[11];
        nv[0] = a;
        #pragma unroll
        for (int i = 0; i < 4; i++) nv[1 + i] = t1 * dz[i];
        #pragma unroll
        for (int p = 0; p < 6; p++)
            nv[5 + p] = -2.0f * a * t1 * dz[PI[p]] * dz[PJ[p]];
        #pragma unroll
        for (int p = 0; p < 5; p++) sh[p][c] = make_float2(nv[2 * p], nv[2 * p + 1]);
        sh[5][c] = make_float2(nv[10], 0.0f);
    }
    __syncwarp();

    // ---------------- 5 hidden layers (128 -> 128) ----------------
    for (int l = 0; l < 5; l++) {
        const float* __restrict__ W  = Wh + l * D * D;
        const float* __restrict__ bl = bh + l * D;

        float2 acc[4][NP];
        #pragma unroll
        for (int q = 0; q < 4; q++)
            #pragma unroll
            for (int p = 0; p < NP; p++) acc[q][p] = make_float2(0.0f, 0.0f);

        #pragma unroll 2
        for (int kk = 0; kk < D / 2; kk++) {
            const float* __restrict__ Wk = W + (2 * kk) * D;
            float2 s0[4], s1[4];
            #pragma unroll
            for (int q = 0; q < 4; q++) {
                const float w0 = Wk[lane + 32 * q];
                const float w1 = Wk[D + lane + 32 * q];
                s0[q] = make_float2(w0, w0);
                s1[q] = make_float2(w1, w1);
            }
            #pragma unroll
            for (int p = 0; p < NP; p++) {
                const float4 L = *reinterpret_cast<const float4*>(&sh[p][2 * kk]);
                const float2 pk0 = make_float2(L.x, L.y);
                const float2 pk1 = make_float2(L.z, L.w);
                #pragma unroll
                for (int q = 0; q < 4; q++) {
                    acc[q][p] = ffma2(pk0, s0[q], acc[q][p]);
                    acc[q][p] = ffma2(pk1, s1[q], acc[q][p]);
                }
            }
        }
        __syncwarp();

        #pragma unroll
        for (int q = 0; q < 4; q++) {
            const int c = lane + 32 * q;
            const float zv[11] = {
                acc[q][0].x, acc[q][0].y, acc[q][1].x, acc[q][1].y,
                acc[q][2].x, acc[q][2].y, acc[q][3].x, acc[q][3].y,
                acc[q][4].x, acc[q][4].y, acc[q][5].x };
            const float a  = tanhf(ac * (zv[0] + bl[c]));
            const float t1 = 1.0f - a * a;
            float dz[4];
            #pragma unroll
            for (int i = 0; i < 4; i++) dz[i] = ac * zv[1 + i];
            float nv[11];
            nv[0] = a;
            #pragma unroll
            for (int i = 0; i < 4; i++) nv[1 + i] = t1 * dz[i];
            #pragma unroll
            for (int p = 0; p < 6; p++) {
                const float d2z = ac * zv[5 + p];
                nv[5 + p] = t1 * (d2z - 2.0f * a * dz[PI[p]] * dz[PJ[p]]);
            }
            #pragma unroll
            for (int p = 0; p < 5; p++) sh[p][c] = make_float2(nv[2 * p], nv[2 * p + 1]);
            sh[5][c] = make_float2(nv[10], 0.0f);
        }
        __syncwarp();
    }

    // ---------------- Output layer: 44 dot products, 1 per lane ----------------
    #pragma unroll
    for (int r = 0; r < 2; r++) {
        const int cb = lane + 32 * r;
        if (cb < 44) {
            const int v = cb >> 2;
            const int o = cb & 3;
            const int pr = v >> 1;
            const int hi = v & 1;
            float s = 0.0f;
            for (int k = 0; k < D; k++) {
                const float2 e = sh[pr][k];
                s = fmaf(hi ? e.y : e.x, Wout[k * 4 + o], s);
            }
            red[pt_l][cb] = s;
        }
    }
    __syncwarp();

    if (lane == 0) {
        const float* rd = red[pt_l];
        float Y[4];
        #pragma unroll
        for (int o = 0; o < 4; o++) Y[o] = rd[o] + bout[o];
        const float u = Y[0], v = Y[1], w = Y[2];
        const float u_x = rd[4],  u_y = rd[8],  u_z = rd[12], u_t = rd[16];
        const float v_x = rd[5],  v_y = rd[9],  v_z = rd[13], v_t = rd[17];
        const float w_x = rd[6],  w_y = rd[10], w_z = rd[14], w_t = rd[18];
        const float p_x = rd[7],  p_y = rd[11], p_z = rd[15];
        // second order combos: red[(5+p)*4+o], p: 0=xx 1=yy 2=zz 3=xy 4=xz 5=yz
        const float Hxx_u = rd[20], Hyy_u = rd[24], Hzz_u = rd[28], Hxy_u = rd[32], Hxz_u = rd[36];
        const float Hxx_v = rd[21], Hyy_v = rd[25], Hzz_v = rd[29], Hxy_v = rd[33], Hyz_v = rd[41];
        const float Hxx_w = rd[22], Hyy_w = rd[26], Hzz_w = rd[30], Hxz_w = rd[38], Hyz_w = rd[42];

        const float tau_x = 2.0f * Hxx_u + Hyy_u + Hxy_v + Hzz_u + Hxz_w;
        const float tau_y = Hxy_u + Hxx_v + 2.0f * Hyy_v + Hzz_v + Hyz_w;
        const float tau_z = Hxz_u + Hxx_w + Hyz_v + Hyy_w + 2.0f * Hzz_w;

        out[0 * N + n] = u_x + v_y + w_z;
        out[1 * N + n] = u_t + (u * u_x + v * u_y + w * u_z) + p_x - tau_x;
        out[2 * N + n] = v_t + (u * v_x + v * v_y + w * v_z) + p_y - tau_y;
        out[3 * N + n] = w_t + (u * w_x + v * w_y + w * w_z) + p_z - tau_z + 98.9f;
    }
}

extern "C" void kernel_launch(void* const* d_in, const int* in_sizes, int n_in,
                              void* d_out, int out_size)
{
    const float* x    = (const float*)d_in[0];
    const float* y    = (const float*)d_in[1];
    const float* z    = (const float*)d_in[2];
    const float* t    = (const float*)d_in[3];
    const float* W0   = (const float*)d_in[4];
    const float* b0   = (const float*)d_in[5];
    const float* Wh   = (const float*)d_in[6];
    const float* bh   = (const float*)d_in[7];
    const float* Wout = (const float*)d_in[8];
    const float* bout = (const float*)d_in[9];
    const float* ac   = (const float*)d_in[10];

    const int N = in_sizes[0];
    pinn_kernel<<<(N + 3) / 4, 128>>>(x, y, z, t, W0, b0, Wh, bh, Wout, bout, ac,
                                      (float*)d_out, N);
}

// round 6
// speedup vs baseline: 2.3417x; 1.4823x over previous
#include <cuda_runtime.h>
#include <cuda_bf16.h>
#include <cstdint>

#define PTSB 16          // points per CTA
#define RPP  12          // padded rows per point (11 used)
#define MR   192         // M rows = PTSB*RPP = 12 m16-tiles
#define KD   128
#define ND   128
#define THREADS 256

#define SA 136           // act row stride (bf16 elems), 128 + 8 pad
#define SW 136           // weight row stride (bf16 elems)
#define SZ 132           // fp32 dump row stride

// smem byte offsets
#define ACT_H 0
#define ACT_L 52224                      // 192*136*2
#define WB    104448                     // weight region base (also Z dump / reused)
#define W_H   104448
#define W_L   139264                     // +128*136*2
#define WOUTS 174080                     // 512 floats
#define BOUTS 176128                     // 4 floats
#define REDS  176144                     // 704 floats
#define SMEM_TOTAL 179200

static __device__ __forceinline__ uint32_t smem_u32(const void* p) {
    uint32_t a;
    asm("{ .reg .u64 t; cvta.to.shared.u64 t, %1; cvt.u32.u64 %0, t; }" : "=r"(a) : "l"(p));
    return a;
}
static __device__ __forceinline__ void ldm_x4(uint32_t* r, uint32_t addr) {
    asm volatile("ldmatrix.sync.aligned.m8n8.x4.shared.b16 {%0,%1,%2,%3}, [%4];"
        : "=r"(r[0]), "=r"(r[1]), "=r"(r[2]), "=r"(r[3]) : "r"(addr));
}
static __device__ __forceinline__ void ldm_x4_t(uint32_t* r, uint32_t addr) {
    asm volatile("ldmatrix.sync.aligned.m8n8.x4.trans.shared.b16 {%0,%1,%2,%3}, [%4];"
        : "=r"(r[0]), "=r"(r[1]), "=r"(r[2]), "=r"(r[3]) : "r"(addr));
}
static __device__ __forceinline__ void mma_bf16(float* c, const uint32_t* a, const uint32_t* b) {
    asm volatile("mma.sync.aligned.m16n8k16.row.col.f32.bf16.bf16.f32 "
        "{%0,%1,%2,%3}, {%4,%5,%6,%7}, {%8,%9}, {%0,%1,%2,%3};"
        : "+f"(c[0]), "+f"(c[1]), "+f"(c[2]), "+f"(c[3])
        : "r"(a[0]), "r"(a[1]), "r"(a[2]), "r"(a[3]), "r"(b[0]), "r"(b[1]));
}

static __device__ __forceinline__ void split_act(char* sm, int row, int col, float w) {
    __nv_bfloat16 h  = __float2bfloat16(w);
    __nv_bfloat16 lo = __float2bfloat16(w - __bfloat162float(h));
    *(__nv_bfloat16*)(sm + ACT_H + (row * SA + col) * 2) = h;
    *(__nv_bfloat16*)(sm + ACT_L + (row * SA + col) * 2) = lo;
}

__global__ __launch_bounds__(THREADS, 1)
void pinn_mma(const float* __restrict__ x, const float* __restrict__ y,
              const float* __restrict__ z, const float* __restrict__ tt,
              const float* __restrict__ W0, const float* __restrict__ b0,
              const float* __restrict__ Wh, const float* __restrict__ bh,
              const float* __restrict__ Wout, const float* __restrict__ bout,
              const float* __restrict__ act_coeff,
              float* __restrict__ out, int N)
{
    extern __shared__ __align__(1024) char sm[];
    const int tid  = threadIdx.x;
    const int lane = tid & 31;
    const int wid  = tid >> 5;
    const int mg   = wid >> 1;        // 0..3 : owns m-tiles 3mg..3mg+2
    const int nh   = wid & 1;         // 0..1 : owns cols [64nh, 64nh+64)
    const uint32_t sbase = smem_u32(sm);
    const float ac = __ldg(act_coeff);

    const int PI[6] = {0, 1, 2, 0, 0, 1};
    const int PJ[6] = {0, 1, 2, 1, 2, 2};

    float* wout_s = (float*)(sm + WOUTS);
    float* bout_s = (float*)(sm + BOUTS);
    float* red    = (float*)(sm + REDS);
    // FIX: grid-stride load of all 512 Wout floats; 4-thread load of bout.
    for (int i = tid; i < 512; i += THREADS) wout_s[i] = __ldg(&Wout[i]);
    if (tid < 4) bout_s[tid] = __ldg(&bout[tid]);

    const int g0 = blockIdx.x * PTSB;

    // ---------------- layer 0 init: 8 (point, feature) items per thread ----------------
    #pragma unroll
    for (int i = 0; i < 8; i++) {
        const int item = tid + THREADS * i;
        const int p = item >> 7, m = item & 127;
        const int g = g0 + p;
        const float X0 = __ldg(x + g), X1 = __ldg(y + g), X2 = __ldg(z + g);
        const float X3 = 2.0f * __ldg(tt + g) - 1.0f;
        const float w0j = __ldg(&W0[m]), w1j = __ldg(&W0[128 + m]);
        const float w2j = __ldg(&W0[256 + m]), w3j = __ldg(&W0[384 + m]);
        const float zz = ac * (X0 * w0j + X1 * w1j + X2 * w2j + X3 * w3j + __ldg(&b0[m]));
        const float a  = tanhf(zz);
        const float t1 = 1.0f - a * a;
        const float dz[4] = {ac * w0j, ac * w1j, ac * w2j, 2.0f * ac * w3j};
        float nv[11];
        nv[0] = a;
        #pragma unroll
        for (int q = 0; q < 4; q++) nv[1 + q] = t1 * dz[q];
        #pragma unroll
        for (int q = 0; q < 6; q++) nv[5 + q] = -2.0f * a * t1 * dz[PI[q]] * dz[PJ[q]];
        #pragma unroll
        for (int v = 0; v < 11; v++) split_act(sm, RPP * p + v, m, nv[v]);
    }
    __syncthreads();

    // ---------------- load + split layer-0 weights ----------------
    {
        const float* Wl = Wh;
        for (int i = tid; i < KD * ND; i += THREADS) {
            const int k = i >> 7, n = i & 127;
            const float w = __ldg(&Wl[i]);
            __nv_bfloat16 h  = __float2bfloat16(w);
            __nv_bfloat16 lo = __float2bfloat16(w - __bfloat162float(h));
            *(__nv_bfloat16*)(sm + W_H + (k * SW + n) * 2) = h;
            *(__nv_bfloat16*)(sm + W_L + (k * SW + n) * 2) = lo;
        }
    }
    __syncthreads();

    // ---------------- 5 hidden layers ----------------
    for (int l = 0; l < 5; l++) {
        float acc[3][8][4];
        #pragma unroll
        for (int j = 0; j < 3; j++)
            #pragma unroll
            for (int nt = 0; nt < 8; nt++)
                #pragma unroll
                for (int s = 0; s < 4; s++) acc[j][nt][s] = 0.0f;

        const int arow = lane & 15, acol8 = 8 * (lane >> 4);

        #pragma unroll 1
        for (int kt = 0; kt < 8; kt++) {
            const int k0 = 16 * kt;
            uint32_t bh_[4][4], bl_[4][4];
            #pragma unroll
            for (int q = 0; q < 4; q++) {
                const uint32_t boff = ((uint32_t)(k0 + arow) * SW + nh * 64 + 16 * q + acol8) * 2;
                ldm_x4_t(bh_[q], sbase + W_H + boff);
                ldm_x4_t(bl_[q], sbase + W_L + boff);
            }
            #pragma unroll
            for (int j = 0; j < 3; j++) {
                const uint32_t aoff = ((uint32_t)(16 * (3 * mg + j) + arow) * SA + k0 + acol8) * 2;
                uint32_t ah[4], al[4];
                ldm_x4(ah, sbase + ACT_H + aoff);
                ldm_x4(al, sbase + ACT_L + aoff);
                #pragma unroll
                for (int q = 0; q < 4; q++) {
                    #pragma unroll
                    for (int s = 0; s < 2; s++) {
                        const uint32_t* bhp = &bh_[q][2 * s];
                        const uint32_t* blp = &bl_[q][2 * s];
                        float* cc = acc[j][2 * q + s];
                        mma_bf16(cc, ah, bhp);
                        mma_bf16(cc, ah, blp);
                        mma_bf16(cc, al, bhp);
                    }
                }
            }
        }
        __syncthreads();   // all GEMM reads of acts + weights complete

        // epilogue in two halves (Z dump reuses weight region: 96 x 132 fp32)
        float* Zf = (float*)(sm + WB);
        #pragma unroll 1
        for (int half = 0; half < 2; half++) {
            if ((mg >> 1) == half) {
                const int g8 = lane >> 2, tg = lane & 3;
                #pragma unroll
                for (int j = 0; j < 3; j++) {
                    const int rbase = 16 * (3 * mg + j) - 96 * half + g8;
                    #pragma unroll
                    for (int nt = 0; nt < 8; nt++) {
                        const int c0 = nh * 64 + nt * 8 + 2 * tg;
                        *(float2*)&Zf[rbase * SZ + c0]       = make_float2(acc[j][nt][0], acc[j][nt][1]);
                        *(float2*)&Zf[(rbase + 8) * SZ + c0] = make_float2(acc[j][nt][2], acc[j][nt][3]);
                    }
                }
            }
            __syncthreads();
            // mix: 8 points x 128 features = 1024 items / 256 threads
            #pragma unroll
            for (int i = 0; i < 4; i++) {
                const int item = tid + THREADS * i;
                const int p = item >> 7, m = item & 127;
                const int pg = 8 * half + p;
                float zv[11];
                #pragma unroll
                for (int v = 0; v < 11; v++) zv[v] = Zf[(RPP * p + v) * SZ + m];
                const float bias = __ldg(&bh[l * ND + m]);
                const float a  = tanhf(ac * (zv[0] + bias));
                const float t1 = 1.0f - a * a;
                float dz[4];
                #pragma unroll
                for (int q = 0; q < 4; q++) dz[q] = ac * zv[1 + q];
                float nv[11];
                nv[0] = a;
                #pragma unroll
                for (int q = 0; q < 4; q++) nv[1 + q] = t1 * dz[q];
                #pragma unroll
                for (int q = 0; q < 6; q++)
                    nv[5 + q] = t1 * (ac * zv[5 + q] - 2.0f * a * dz[PI[q]] * dz[PJ[q]]);
                if (l < 4) {
                    #pragma unroll
                    for (int v = 0; v < 11; v++) split_act(sm, RPP * pg + v, m, nv[v]);
                } else {
                    float* F = (float*)(sm + ACT_H);
                    #pragma unroll
                    for (int v = 0; v < 11; v++) F[(RPP * pg + v) * SZ + m] = nv[v];
                }
            }
            __syncthreads();
        }

        if (l < 4) {
            const float* Wl = Wh + (l + 1) * KD * ND;
            for (int i = tid; i < KD * ND; i += THREADS) {
                const int k = i >> 7, n = i & 127;
                const float w = __ldg(&Wl[i]);
                __nv_bfloat16 h  = __float2bfloat16(w);
                __nv_bfloat16 lo = __float2bfloat16(w - __bfloat162float(h));
                *(__nv_bfloat16*)(sm + W_H + (k * SW + n) * 2) = h;
                *(__nv_bfloat16*)(sm + W_L + (k * SW + n) * 2) = lo;
            }
            __syncthreads();
        }
    }

    // ---------------- output layer: 16 pts x 44 dots of length 128 ----------------
    const float* F = (const float*)(sm + ACT_H);
    for (int c = tid; c < PTSB * 44; c += THREADS) {
        const int p = c / 44, r44 = c % 44, v = r44 >> 2, o = r44 & 3;
        const float* Fr = F + (RPP * p + v) * SZ;
        float s = 0.0f;
        #pragma unroll 8
        for (int m = 0; m < ND; m++) s = fmaf(Fr[m], wout_s[m * 4 + o], s);
        red[c] = s;
    }
    __syncthreads();

    if (tid < PTSB) {
        const int p = tid, g = g0 + p;
        const float* rd = red + p * 44;
        const float u = rd[0] + bout_s[0];
        const float v = rd[1] + bout_s[1];
        const float w = rd[2] + bout_s[2];
        const float u_x = rd[4],  u_y = rd[8],  u_z = rd[12], u_t = rd[16];
        const float v_x = rd[5],  v_y = rd[9],  v_z = rd[13], v_t = rd[17];
        const float w_x = rd[6],  w_y = rd[10], w_z = rd[14], w_t = rd[18];
        const float p_x = rd[7],  p_y = rd[11], p_z = rd[15];
        const float Hxx_u = rd[20], Hyy_u = rd[24], Hzz_u = rd[28], Hxy_u = rd[32], Hxz_u = rd[36];
        const float Hxx_v = rd[21], Hyy_v = rd[25], Hzz_v = rd[29], Hxy_v = rd[33], Hyz_v = rd[41];
        const float Hxx_w = rd[22], Hyy_w = rd[26], Hzz_w = rd[30], Hxz_w = rd[38], Hyz_w = rd[42];
        const float tau_x = 2.0f * Hxx_u + Hyy_u + Hxy_v + Hzz_u + Hxz_w;
        const float tau_y = Hxy_u + Hxx_v + 2.0f * Hyy_v + Hzz_v + Hyz_w;
        const float tau_z = Hxz_u + Hxx_w + Hyz_v + Hyy_w + 2.0f * Hzz_w;
        out[0 * N + g] = u_x + v_y + w_z;
        out[1 * N + g] = u_t + (u * u_x + v * u_y + w * u_z) + p_x - tau_x;
        out[2 * N + g] = v_t + (u * v_x + v * v_y + w * v_z) + p_y - tau_y;
        out[3 * N + g] = w_t + (u * w_x + v * w_y + w * w_z) + p_z - tau_z + 98.9f;
    }
}

extern "C" void kernel_launch(void* const* d_in, const int* in_sizes, int n_in,
                              void* d_out, int out_size)
{
    const float* x    = (const float*)d_in[0];
    const float* y    = (const float*)d_in[1];
    const float* z    = (const float*)d_in[2];
    const float* t    = (const float*)d_in[3];
    const float* W0   = (const float*)d_in[4];
    const float* b0   = (const float*)d_in[5];
    const float* Wh   = (const float*)d_in[6];
    const float* bh   = (const float*)d_in[7];
    const float* Wout = (const float*)d_in[8];
    const float* bout = (const float*)d_in[9];
    const float* ac   = (const float*)d_in[10];
    const int N = in_sizes[0];

    cudaFuncSetAttribute(pinn_mma, cudaFuncAttributeMaxDynamicSharedMemorySize, SMEM_TOTAL);
    pinn_mma<<<N / PTSB, THREADS, SMEM_TOTAL>>>(x, y, z, t, W0, b0, Wh, bh, Wout, bout, ac,
                                                (float*)d_out, N);
}

// round 8
// speedup vs baseline: 2.7695x; 1.1827x over previous
#include <cuda_runtime.h>
#include <cuda_bf16.h>
#include <cstdint>

#define PTSB 8           // points per CTA
#define RPP  12          // padded rows per point (11 used)
#define MR   96          // M rows = 6 m16-tiles
#define KD   128
#define ND   128
#define THREADS 256

// XOR-swizzled regions: row stride 256B (128 bf16), swizzle on 16B chunks
#define ACT_H 0                          // 96*256 = 24576
#define ACT_L 24576
#define W_H   49152                      // 128*256 = 32768
#define W_L   81920
#define SMEM_TOTAL 114688
// Z dump (fp32, stride 132) and red[352] reuse the weight region at W_H.
#define SZ 132

static __device__ __forceinline__ uint32_t smem_u32(const void* p) {
    uint32_t a;
    asm("{ .reg .u64 t; cvta.to.shared.u64 t, %1; cvt.u32.u64 %0, t; }" : "=r"(a) : "l"(p));
    return a;
}
// byte offset of bf16 element (row, col) in a swizzled 128-col region
static __device__ __forceinline__ uint32_t swz(int row, int col) {
    return (uint32_t)row * 256u + (((uint32_t)col * 2u) ^ (((uint32_t)row & 7u) << 4));
}
static __device__ __forceinline__ void ldm_x4(uint32_t* r, uint32_t addr) {
    asm volatile("ldmatrix.sync.aligned.m8n8.x4.shared.b16 {%0,%1,%2,%3}, [%4];"
        : "=r"(r[0]), "=r"(r[1]), "=r"(r[2]), "=r"(r[3]) : "r"(addr));
}
static __device__ __forceinline__ void ldm_x4_t(uint32_t* r, uint32_t addr) {
    asm volatile("ldmatrix.sync.aligned.m8n8.x4.trans.shared.b16 {%0,%1,%2,%3}, [%4];"
        : "=r"(r[0]), "=r"(r[1]), "=r"(r[2]), "=r"(r[3]) : "r"(addr));
}
static __device__ __forceinline__ void mma_bf16(float* c, const uint32_t* a, const uint32_t* b) {
    asm volatile("mma.sync.aligned.m16n8k16.row.col.f32.bf16.bf16.f32 "
        "{%0,%1,%2,%3}, {%4,%5,%6,%7}, {%8,%9}, {%0,%1,%2,%3};"
        : "+f"(c[0]), "+f"(c[1]), "+f"(c[2]), "+f"(c[3])
        : "r"(a[0]), "r"(a[1]), "r"(a[2]), "r"(a[3]), "r"(b[0]), "r"(b[1]));
}
static __device__ __forceinline__ void split_act(char* sm, int row, int col, float w) {
    __nv_bfloat16 h  = __float2bfloat16(w);
    __nv_bfloat16 lo = __float2bfloat16(w - __bfloat162float(h));
    const uint32_t o = swz(row, col);
    *(__nv_bfloat16*)(sm + ACT_H + o) = h;
    *(__nv_bfloat16*)(sm + ACT_L + o) = lo;
}

__global__ __launch_bounds__(THREADS, 2)
void pinn_mma(const float* __restrict__ x, const float* __restrict__ y,
              const float* __restrict__ z, const float* __restrict__ tt,
              const float* __restrict__ W0, const float* __restrict__ b0,
              const float* __restrict__ Wh, const float* __restrict__ bh,
              const float* __restrict__ Wout, const float* __restrict__ bout,
              const float* __restrict__ act_coeff,
              float* __restrict__ out, int N)
{
    extern __shared__ __align__(1024) char sm[];
    const int tid  = threadIdx.x;
    const int lane = tid & 31;
    const int wid  = tid >> 5;
    const int mg   = wid >> 2;        // 0..1 : owns m-tiles 3mg..3mg+2
    const int nq   = wid & 3;         // 0..3 : owns cols [32nq, 32nq+32)
    const uint32_t sbase = smem_u32(sm);
    const float ac = __ldg(act_coeff);

    const int PI[6] = {0, 1, 2, 0, 0, 1};
    const int PJ[6] = {0, 1, 2, 1, 2, 2};

    const int g0 = blockIdx.x * PTSB;

    // ---------------- layer 0 init: 4 (point, feature) items per thread ----------------
    #pragma unroll
    for (int i = 0; i < 4; i++) {
        const int item = tid + THREADS * i;
        const int p = item >> 7, m = item & 127;
        const int g = g0 + p;
        const float X0 = __ldg(x + g), X1 = __ldg(y + g), X2 = __ldg(z + g);
        const float X3 = 2.0f * __ldg(tt + g) - 1.0f;
        const float w0j = __ldg(&W0[m]), w1j = __ldg(&W0[128 + m]);
        const float w2j = __ldg(&W0[256 + m]), w3j = __ldg(&W0[384 + m]);
        const float zz = ac * (X0 * w0j + X1 * w1j + X2 * w2j + X3 * w3j + __ldg(&b0[m]));
        const float a  = tanhf(zz);
        const float t1 = 1.0f - a * a;
        const float dz[4] = {ac * w0j, ac * w1j, ac * w2j, 2.0f * ac * w3j};
        float nv[11];
        nv[0] = a;
        #pragma unroll
        for (int q = 0; q < 4; q++) nv[1 + q] = t1 * dz[q];
        #pragma unroll
        for (int q = 0; q < 6; q++) nv[5 + q] = -2.0f * a * t1 * dz[PI[q]] * dz[PJ[q]];
        #pragma unroll
        for (int v = 0; v < 11; v++) split_act(sm, RPP * p + v, m, nv[v]);
    }

    // ---------------- load + split layer-0 weights (float4, 16 iters/thread) ----------------
    {
        const float4* Wl = (const float4*)Wh;
        for (int i4 = tid; i4 < KD * ND / 4; i4 += THREADS) {
            const int k = i4 >> 5, n4 = (i4 & 31) * 4;
            const float4 w = __ldg(&Wl[i4]);
            __nv_bfloat162 h01 = make_bfloat162(__float2bfloat16(w.x), __float2bfloat16(w.y));
            __nv_bfloat162 h23 = make_bfloat162(__float2bfloat16(w.z), __float2bfloat16(w.w));
            __nv_bfloat162 l01 = make_bfloat162(__float2bfloat16(w.x - __bfloat162float(h01.x)),
                                                __float2bfloat16(w.y - __bfloat162float(h01.y)));
            __nv_bfloat162 l23 = make_bfloat162(__float2bfloat16(w.z - __bfloat162float(h23.x)),
                                                __float2bfloat16(w.w - __bfloat162float(h23.y)));
            const uint32_t o = swz(k, n4);
            *(__nv_bfloat162*)(sm + W_H + o)     = h01;
            *(__nv_bfloat162*)(sm + W_H + o + 4) = h23;
            *(__nv_bfloat162*)(sm + W_L + o)     = l01;
            *(__nv_bfloat162*)(sm + W_L + o + 4) = l23;
        }
    }
    __syncthreads();

    // ---------------- 5 hidden layers ----------------
    for (int l = 0; l < 5; l++) {
        float acc[3][4][4];
        #pragma unroll
        for (int j = 0; j < 3; j++)
            #pragma unroll
            for (int nt = 0; nt < 4; nt++)
                #pragma unroll
                for (int s = 0; s < 4; s++) acc[j][nt][s] = 0.0f;

        const int arow = lane & 15, hi16 = lane >> 4;

        #pragma unroll 1
        for (int kt = 0; kt < 8; kt++) {
            const int k0 = 16 * kt;
            // B fragments: 32 cols = 2 x (16-col ldmatrix.trans), hi & lo
            uint32_t bh_[2][4], bl_[2][4];
            #pragma unroll
            for (int q2 = 0; q2 < 2; q2++) {
                const int krow = k0 + arow;
                const uint32_t cb = (uint32_t)(32 * nq + 16 * q2) * 2u + 16u * hi16;
                const uint32_t ba = (uint32_t)krow * 256u + (cb ^ (((uint32_t)krow & 7u) << 4));
                ldm_x4_t(bh_[q2], sbase + W_H + ba);
                ldm_x4_t(bl_[q2], sbase + W_L + ba);
            }
            #pragma unroll
            for (int j = 0; j < 3; j++) {
                const int R = 16 * (3 * mg + j) + arow;
                const uint32_t cb = (uint32_t)(2 * k0) + 16u * hi16;
                const uint32_t aa = (uint32_t)R * 256u + (cb ^ (((uint32_t)R & 7u) << 4));
                uint32_t ah[4], al[4];
                ldm_x4(ah, sbase + ACT_H + aa);
                ldm_x4(al, sbase + ACT_L + aa);
                #pragma unroll
                for (int q2 = 0; q2 < 2; q2++) {
                    #pragma unroll
                    for (int s = 0; s < 2; s++) {
                        const uint32_t* bhp = &bh_[q2][2 * s];
                        const uint32_t* blp = &bl_[q2][2 * s];
                        float* cc = acc[j][2 * q2 + s];
                        mma_bf16(cc, ah, bhp);
                        mma_bf16(cc, ah, blp);
                        mma_bf16(cc, al, bhp);
                    }
                }
            }
        }
        __syncthreads();   // GEMM reads of acts + weights complete

        // ---- dump C (fp32) into weight region ----
        float* Zf = (float*)(sm + W_H);
        {
            const int g8 = lane >> 2, tg = lane & 3;
            #pragma unroll
            for (int j = 0; j < 3; j++) {
                const int rbase = 16 * (3 * mg + j) + g8;
                #pragma unroll
                for (int nt = 0; nt < 4; nt++) {
                    const int c0 = 32 * nq + nt * 8 + 2 * tg;
                    *(float2*)&Zf[rbase * SZ + c0]       = make_float2(acc[j][nt][0], acc[j][nt][1]);
                    *(float2*)&Zf[(rbase + 8) * SZ + c0] = make_float2(acc[j][nt][2], acc[j][nt][3]);
                }
            }
        }
        __syncthreads();

        // ---- mix: 8 points x 128 features ----
        #pragma unroll
        for (int i = 0; i < 4; i++) {
            const int item = tid + THREADS * i;
            const int p = item >> 7, m = item & 127;
            float zv[11];
            #pragma unroll
            for (int v = 0; v < 11; v++) zv[v] = Zf[(RPP * p + v) * SZ + m];
            const float bias = __ldg(&bh[l * ND + m]);
            const float a  = tanhf(ac * (zv[0] + bias));
            const float t1 = 1.0f - a * a;
            float dz[4];
            #pragma unroll
            for (int q = 0; q < 4; q++) dz[q] = ac * zv[1 + q];
            float nv[11];
            nv[0] = a;
            #pragma unroll
            for (int q = 0; q < 4; q++) nv[1 + q] = t1 * dz[q];
            #pragma unroll
            for (int q = 0; q < 6; q++)
                nv[5 + q] = t1 * (ac * zv[5 + q] - 2.0f * a * dz[PI[q]] * dz[PJ[q]]);
            if (l < 4) {
                #pragma unroll
                for (int v = 0; v < 11; v++) split_act(sm, RPP * p + v, m, nv[v]);
            } else {
                float* F = (float*)(sm + ACT_H);   // fp32 finals, stride 128
                #pragma unroll
                for (int v = 0; v < 11; v++) F[(RPP * p + v) * 128 + m] = nv[v];
            }
        }
        __syncthreads();

        if (l < 4) {
            const float4* Wl = (const float4*)(Wh + (l + 1) * KD * ND);
            for (int i4 = tid; i4 < KD * ND / 4; i4 += THREADS) {
                const int k = i4 >> 5, n4 = (i4 & 31) * 4;
                const float4 w = __ldg(&Wl[i4]);
                __nv_bfloat162 h01 = make_bfloat162(__float2bfloat16(w.x), __float2bfloat16(w.y));
                __nv_bfloat162 h23 = make_bfloat162(__float2bfloat16(w.z), __float2bfloat16(w.w));
                __nv_bfloat162 l01 = make_bfloat162(__float2bfloat16(w.x - __bfloat162float(h01.x)),
                                                    __float2bfloat16(w.y - __bfloat162float(h01.y)));
                __nv_bfloat162 l23 = make_bfloat162(__float2bfloat16(w.z - __bfloat162float(h23.x)),
                                                    __float2bfloat16(w.w - __bfloat162float(h23.y)));
                const uint32_t o = swz(k, n4);
                *(__nv_bfloat162*)(sm + W_H + o)     = h01;
                *(__nv_bfloat162*)(sm + W_H + o + 4) = h23;
                *(__nv_bfloat162*)(sm + W_L + o)     = l01;
                *(__nv_bfloat162*)(sm + W_L + o + 4) = l23;
            }
            __syncthreads();
        }
    }

    // ---------------- output layer: 8 pts x 44 dots of length 128 ----------------
    const float* F = (const float*)(sm + ACT_H);
    float* red = (float*)(sm + W_H);        // weight region dead now
    for (int c = tid; c < PTSB * 44; c += THREADS) {
        const int p = c / 44, r44 = c % 44, v = r44 >> 2, o = r44 & 3;
        const float* Fr = F + (RPP * p + v) * 128;
        float s = 0.0f;
        #pragma unroll 8
        for (int i = 0; i < ND; i++) {
            const int m = (tid + i) & (ND - 1);
            s = fmaf(Fr[m], __ldg(&Wout[m * 4 + o]), s);
        }
        red[c] = s;
    }
    __syncthreads();

    if (tid < PTSB) {
        const int p = tid, g = g0 + p;
        const float* rd = red + p * 44;
        const float u = rd[0] + __ldg(&bout[0]);
        const float v = rd[1] + __ldg(&bout[1]);
        const float w = rd[2] + __ldg(&bout[2]);
        const float u_x = rd[4],  u_y = rd[8],  u_z = rd[12], u_t = rd[16];
        const float v_x = rd[5],  v_y = rd[9],  v_z = rd[13], v_t = rd[17];
        const float w_x = rd[6],  w_y = rd[10], w_z = rd[14], w_t = rd[18];
        const float p_x = rd[7],  p_y = rd[11], p_z = rd[15];
        const float Hxx_u = rd[20], Hyy_u = rd[24], Hzz_u = rd[28], Hxy_u = rd[32], Hxz_u = rd[36];
        const float Hxx_v = rd[21], Hyy_v = rd[25], Hzz_v = rd[29], Hxy_v = rd[33], Hyz_v = rd[41];
        const float Hxx_w = rd[22], Hyy_w = rd[26], Hzz_w = rd[30], Hxz_w = rd[38], Hyz_w = rd[42];
        const float tau_x = 2.0f * Hxx_u + Hyy_u + Hxy_v + Hzz_u + Hxz_w;
        const float tau_y = Hxy_u + Hxx_v + 2.0f * Hyy_v + Hzz_v + Hyz_w;
        const float tau_z = Hxz_u + Hxx_w + Hyz_v + Hyy_w + 2.0f * Hzz_w;
        out[0 * N + g] = u_x + v_y + w_z;
        out[1 * N + g] = u_t + (u * u_x + v * u_y + w * u_z) + p_x - tau_x;
        out[2 * N + g] = v_t + (u * v_x + v * v_y + w * v_z) + p_y - tau_y;
        out[3 * N + g] = w_t + (u * w_x + v * w_y + w * w_z) + p_z - tau_z + 98.9f;
    }
}

extern "C" void kernel_launch(void* const* d_in, const int* in_sizes, int n_in,
                              void* d_out, int out_size)
{
    const float* x    = (const float*)d_in[0];
    const float* y    = (const float*)d_in[1];
    const float* z    = (const float*)d_in[2];
    const float* t    = (const float*)d_in[3];
    const float* W0   = (const float*)d_in[4];
    const float* b0   = (const float*)d_in[5];
    const float* Wh   = (const float*)d_in[6];
    const float* bh   = (const float*)d_in[7];
    const float* Wout = (const float*)d_in[8];
    const float* bout = (const float*)d_in[9];
    const float* ac   = (const float*)d_in[10];
    const int N = in_sizes[0];

    cudaFuncSetAttribute(pinn_mma, cudaFuncAttributeMaxDynamicSharedMemorySize, SMEM_TOTAL);
    pinn_mma<<<N / PTSB, THREADS, SMEM_TOTAL>>>(x, y, z, t, W0, b0, Wh, bh, Wout, bout, ac,
                                                (float*)d_out, N);
}

// round 10
// speedup vs baseline: 3.3562x; 1.2118x over previous
#include <cuda_runtime.h>
#include <cuda_bf16.h>
#include <cstdint>

#define PTSB 8
#define RPP  12
#define KD   128
#define ND   128
#define THREADS 256

// region A: acts hi/lo (bf16, swizzled) OR Z/F fp32 skewed (48KB exactly)
#define ACT_H 0
#define ACT_L 24576
// region W: weights hi/lo (bf16, swizzled) (64KB); red[] reuses it at the end
#define W_H   49152
#define W_L   81920
#define SMEM_TOTAL 114688

__device__ __align__(16) __nv_bfloat16 g_wh_hi[5 * KD * ND];
__device__ __align__(16) __nv_bfloat16 g_wh_lo[5 * KD * ND];

static __device__ __forceinline__ uint32_t smem_u32(const void* p) {
    uint32_t a;
    asm("{ .reg .u64 t; cvta.to.shared.u64 t, %1; cvt.u32.u64 %0, t; }" : "=r"(a) : "l"(p));
    return a;
}
static __device__ __forceinline__ uint32_t swz(int row, int col) {   // bf16 elem (row,col), 128-col region
    return (uint32_t)row * 256u + (((uint32_t)col * 2u) ^ (((uint32_t)row & 7u) << 4));
}
static __device__ __forceinline__ void ldm_x4(uint32_t* r, uint32_t addr) {
    asm volatile("ldmatrix.sync.aligned.m8n8.x4.shared.b16 {%0,%1,%2,%3}, [%4];"
        : "=r"(r[0]), "=r"(r[1]), "=r"(r[2]), "=r"(r[3]) : "r"(addr));
}
static __device__ __forceinline__ void ldm_x4_t(uint32_t* r, uint32_t addr) {
    asm volatile("ldmatrix.sync.aligned.m8n8.x4.trans.shared.b16 {%0,%1,%2,%3}, [%4];"
        : "=r"(r[0]), "=r"(r[1]), "=r"(r[2]), "=r"(r[3]) : "r"(addr));
}
static __device__ __forceinline__ void mma_bf16(float* c, const uint32_t* a, const uint32_t* b) {
    asm volatile("mma.sync.aligned.m16n8k16.row.col.f32.bf16.bf16.f32 "
        "{%0,%1,%2,%3}, {%4,%5,%6,%7}, {%8,%9}, {%0,%1,%2,%3};"
        : "+f"(c[0]), "+f"(c[1]), "+f"(c[2]), "+f"(c[3])
        : "r"(a[0]), "r"(a[1]), "r"(a[2]), "r"(a[3]), "r"(b[0]), "r"(b[1]));
}
#define CP16(dst, src) asm volatile("cp.async.cg.shared.global [%0], [%1], 16;" :: "r"(dst), "l"(src))
#define CP_COMMIT()    asm volatile("cp.async.commit_group;" ::: "memory")
#define CP_WAIT0()     asm volatile("cp.async.wait_group 0;" ::: "memory")

static __device__ __forceinline__ void split_act(char* sm, int row, int col, float w) {
    __nv_bfloat16 h  = __float2bfloat16(w);
    __nv_bfloat16 lo = __float2bfloat16(w - __bfloat162float(h));
    const uint32_t o = swz(row, col);
    *(__nv_bfloat16*)(sm + ACT_H + o) = h;
    *(__nv_bfloat16*)(sm + ACT_L + o) = lo;
}
// weight fill for layer l: 2048 16B chunks per region via cp.async
static __device__ __forceinline__ void fill_weights(uint32_t sbase, int l, int tid) {
    const __nv_bfloat16* gh = g_wh_hi + l * KD * ND;
    const __nv_bfloat16* gl = g_wh_lo + l * KD * ND;
    #pragma unroll
    for (int it = 0; it < 8; it++) {
        const int c = tid + THREADS * it;
        const int k = c >> 4, co = (c & 15) << 4;
        const uint32_t doff = (uint32_t)k * 256u + ((uint32_t)co ^ (((uint32_t)k & 7u) << 4));
        const int soff = k * 128 + ((c & 15) << 3);
        CP16(sbase + W_H + doff, gh + soff);
        CP16(sbase + W_L + doff, gl + soff);
    }
    CP_COMMIT();
}

__global__ void pinn_prep(const float* __restrict__ Wh) {
    const int i = blockIdx.x * blockDim.x + threadIdx.x;
    if (i < 5 * KD * ND) {
        const float w = Wh[i];
        const __nv_bfloat16 h = __float2bfloat16(w);
        g_wh_hi[i] = h;
        g_wh_lo[i] = __float2bfloat16(w - __bfloat162float(h));
    }
}

__global__ __launch_bounds__(THREADS, 2)
void pinn_mma(const float* __restrict__ x, const float* __restrict__ y,
              const float* __restrict__ z, const float* __restrict__ tt,
              const float* __restrict__ W0, const float* __restrict__ b0,
              const float* __restrict__ bh,
              const float* __restrict__ Wout, const float* __restrict__ bout,
              const float* __restrict__ act_coeff,
              float* __restrict__ out, int N)
{
    extern __shared__ __align__(1024) char sm[];
    const int tid  = threadIdx.x;
    const int lane = tid & 31;
    const int wid  = tid >> 5;
    const int mg   = wid >> 2;
    const int nq   = wid & 3;
    const uint32_t sbase = smem_u32(sm);
    const float ac = __ldg(act_coeff);

    const int PI[6] = {0, 1, 2, 0, 0, 1};
    const int PJ[6] = {0, 1, 2, 1, 2, 2};

    const int g0 = blockIdx.x * PTSB;

    // prologue: start layer-0 weight fill immediately
    fill_weights(sbase, 0, tid);

    // layer 0 init
    #pragma unroll
    for (int i = 0; i < 4; i++) {
        const int item = tid + THREADS * i;
        const int p = item >> 7, m = item & 127;
        const int g = g0 + p;
        const float X0 = __ldg(x + g), X1 = __ldg(y + g), X2 = __ldg(z + g);
        const float X3 = 2.0f * __ldg(tt + g) - 1.0f;
        const float w0j = __ldg(&W0[m]), w1j = __ldg(&W0[128 + m]);
        const float w2j = __ldg(&W0[256 + m]), w3j = __ldg(&W0[384 + m]);
        const float zz = ac * (X0 * w0j + X1 * w1j + X2 * w2j + X3 * w3j + __ldg(&b0[m]));
        const float a  = tanhf(zz);
        const float t1 = 1.0f - a * a;
        const float dz[4] = {ac * w0j, ac * w1j, ac * w2j, 2.0f * ac * w3j};
        float nv[11];
        nv[0] = a;
        #pragma unroll
        for (int q = 0; q < 4; q++) nv[1 + q] = t1 * dz[q];
        #pragma unroll
        for (int q = 0; q < 6; q++) nv[5 + q] = -2.0f * a * t1 * dz[PI[q]] * dz[PJ[q]];
        #pragma unroll
        for (int v = 0; v < 11; v++) split_act(sm, RPP * p + v, m, nv[v]);
    }
    CP_WAIT0();
    __syncthreads();

    // hoisted GEMM addresses
    const int arow = lane & 15, hi16 = lane >> 4;
    uint32_t bbase[2];
    #pragma unroll
    for (int q2 = 0; q2 < 2; q2++) {
        const uint32_t cb = (uint32_t)(32 * nq + 16 * q2) * 2u + 16u * hi16;
        bbase[q2] = sbase + W_H + (uint32_t)arow * 256u + (cb ^ (((uint32_t)arow & 7u) << 4));
    }
    uint32_t abase[3], axor[3];
    #pragma unroll
    for (int j = 0; j < 3; j++) {
        const int R = 16 * (3 * mg + j) + arow;
        abase[j] = sbase + ACT_H + (uint32_t)R * 256u;
        axor[j]  = ((uint32_t)R & 7u) << 4;
    }

    for (int l = 0; l < 5; l++) {
        float acc[3][4][4];
        #pragma unroll
        for (int j = 0; j < 3; j++)
            #pragma unroll
            for (int nt = 0; nt < 4; nt++)
                #pragma unroll
                for (int s = 0; s < 4; s++) acc[j][nt][s] = 0.0f;

        #pragma unroll 2
        for (int kt = 0; kt < 8; kt++) {
            uint32_t bh_[2][4], bl_[2][4];
            const uint32_t bstep = (uint32_t)kt * 4096u;
            #pragma unroll
            for (int q2 = 0; q2 < 2; q2++) {
                ldm_x4_t(bh_[q2], bbase[q2] + bstep);
                ldm_x4_t(bl_[q2], bbase[q2] + bstep + 32768u);
            }
            const uint32_t acol = 16u * (uint32_t)hi16 + 32u * (uint32_t)kt;
            #pragma unroll
            for (int j = 0; j < 3; j++) {
                const uint32_t aa = abase[j] + (acol ^ axor[j]);
                uint32_t ah[4], al[4];
                ldm_x4(ah, aa);
                ldm_x4(al, aa + 24576u);
                #pragma unroll
                for (int q2 = 0; q2 < 2; q2++) {
                    #pragma unroll
                    for (int s = 0; s < 2; s++) {
                        const uint32_t* bhp = &bh_[q2][2 * s];
                        const uint32_t* blp = &bl_[q2][2 * s];
                        float* cc = acc[j][2 * q2 + s];
                        mma_bf16(cc, ah, bhp);
                        mma_bf16(cc, ah, blp);
                        mma_bf16(cc, al, bhp);
                    }
                }
            }
        }
        __syncthreads();   // acts + weights reads complete

        // prefetch next layer's weights into W region (now dead) — overlaps dump+mix
        if (l < 4) fill_weights(sbase, l + 1, tid);

        // dump C (fp32) into region A, skewed: col' = (col + 4*row) & 127
        float* Zf = (float*)(sm + ACT_H);
        {
            const int g8 = lane >> 2, tg = lane & 3;
            #pragma unroll
            for (int j = 0; j < 3; j++) {
                const int r0 = 16 * (3 * mg + j) + g8;
                #pragma unroll
                for (int nt = 0; nt < 4; nt++) {
                    const int c0 = 32 * nq + nt * 8 + 2 * tg;
                    *(float2*)&Zf[r0 * 128 + ((c0 + 4 * r0) & 127)]
                        = make_float2(acc[j][nt][0], acc[j][nt][1]);
                    const int r1 = r0 + 8;
                    *(float2*)&Zf[r1 * 128 + ((c0 + 4 * r1) & 127)]
                        = make_float2(acc[j][nt][2], acc[j][nt][3]);
                }
            }
        }
        __syncthreads();

        // mix (in-place): unit = (point p, 4 features m4). stage all reads, sync, write.
        {
            const int p = tid >> 5, m4 = (tid & 31) * 4;
            float4 zs[11];
            #pragma unroll
            for (int v = 0; v < 11; v++) {
                const int zr = RPP * p + v;
                zs[v] = *(const float4*)&Zf[zr * 128 + ((m4 + 4 * zr) & 127)];
            }
            __syncthreads();   // all Z reads complete before region A is rewritten

            float nva[11][4];
            #pragma unroll
            for (int e = 0; e < 4; e++) {
                const int m = m4 + e;
                float zvv[11];
                #pragma unroll
                for (int v = 0; v < 11; v++) zvv[v] = ((const float*)&zs[v])[e];
                const float bias = __ldg(&bh[l * ND + m]);
                const float a  = tanhf(ac * (zvv[0] + bias));
                const float t1 = 1.0f - a * a;
                float dz[4];
                #pragma unroll
                for (int q = 0; q < 4; q++) dz[q] = ac * zvv[1 + q];
                nva[0][e] = a;
                #pragma unroll
                for (int q = 0; q < 4; q++) nva[1 + q][e] = t1 * dz[q];
                #pragma unroll
                for (int q = 0; q < 6; q++)
                    nva[5 + q][e] = t1 * (ac * zvv[5 + q] - 2.0f * a * dz[PI[q]] * dz[PJ[q]]);
            }
            if (l < 4) {
                #pragma unroll
                for (int v = 0; v < 11; v++) {
                    const int row = RPP * p + v;
                    const uint32_t o = swz(row, m4);
                    __nv_bfloat162 h01 = make_bfloat162(__float2bfloat16(nva[v][0]),
                                                        __float2bfloat16(nva[v][1]));
                    __nv_bfloat162 h23 = make_bfloat162(__float2bfloat16(nva[v][2]),
                                                        __float2bfloat16(nva[v][3]));
                    __nv_bfloat162 l01 = make_bfloat162(
                        __float2bfloat16(nva[v][0] - __bfloat162float(h01.x)),
                        __float2bfloat16(nva[v][1] - __bfloat162float(h01.y)));
                    __nv_bfloat162 l23 = make_bfloat162(
                        __float2bfloat16(nva[v][2] - __bfloat162float(h23.x)),
                        __float2bfloat16(nva[v][3] - __bfloat162float(h23.y)));
                    *(__nv_bfloat162*)(sm + ACT_H + o)     = h01;
                    *(__nv_bfloat162*)(sm + ACT_H + o + 4) = h23;
                    *(__nv_bfloat162*)(sm + ACT_L + o)     = l01;
                    *(__nv_bfloat162*)(sm + ACT_L + o + 4) = l23;
                }
            } else {
                float* F = (float*)(sm + ACT_H);     // finals, same skewed fp32 layout
                #pragma unroll
                for (int v = 0; v < 11; v++) {
                    const int row = RPP * p + v;
                    *(float4*)&F[row * 128 + ((m4 + 4 * row) & 127)] =
                        make_float4(nva[v][0], nva[v][1], nva[v][2], nva[v][3]);
                }
            }
        }
        CP_WAIT0();
        __syncthreads();
    }

    // output layer: 8 pts x 44 dots of length 128 over skewed F
    const float* F = (const float*)(sm + ACT_H);
    float* red = (float*)(sm + W_H);
    for (int c = tid; c < PTSB * 44; c += THREADS) {
        const int p = c / 44, r44 = c % 44, v = r44 >> 2, o = r44 & 3;
        const int row = RPP * p + v;
        const float* Fr = F + row * 128;
        const int rot = (4 * row) & 127;
        float s = 0.0f;
        #pragma unroll 8
        for (int m = 0; m < ND; m++)
            s = fmaf(Fr[(m + rot) & 127], __ldg(&Wout[m * 4 + o]), s);
        red[c] = s;
    }
    __syncthreads();

    if (tid < PTSB) {
        const int p = tid, g = g0 + p;
        const float* rd = red + p * 44;
        const float u = rd[0] + __ldg(&bout[0]);
        const float v = rd[1] + __ldg(&bout[1]);
        const float w = rd[2] + __ldg(&bout[2]);
        const float u_x = rd[4],  u_y = rd[8],  u_z = rd[12], u_t = rd[16];
        const float v_x = rd[5],  v_y = rd[9],  v_z = rd[13], v_t = rd[17];
        const float w_x = rd[6],  w_y = rd[10], w_z = rd[14], w_t = rd[18];
        const float p_x = rd[7],  p_y = rd[11], p_z = rd[15];
        const float Hxx_u = rd[20], Hyy_u = rd[24], Hzz_u = rd[28], Hxy_u = rd[32], Hxz_u = rd[36];
        const float Hxx_v = rd[21], Hyy_v = rd[25], Hzz_v = rd[29], Hxy_v = rd[33], Hyz_v = rd[41];
        const float Hxx_w = rd[22], Hyy_w = rd[26], Hzz_w = rd[30], Hxz_w = rd[38], Hyz_w = rd[42];
        const float tau_x = 2.0f * Hxx_u + Hyy_u + Hxy_v + Hzz_u + Hxz_w;
        const float tau_y = Hxy_u + Hxx_v + 2.0f * Hyy_v + Hzz_v + Hyz_w;
        const float tau_z = Hxz_u + Hxx_w + Hyz_v + Hyy_w + 2.0f * Hzz_w;
        out[0 * N + g] = u_x + v_y + w_z;
        out[1 * N + g] = u_t + (u * u_x + v * u_y + w * u_z) + p_x - tau_x;
        out[2 * N + g] = v_t + (u * v_x + v * v_y + w * v_z) + p_y - tau_y;
        out[3 * N + g] = w_t + (u * w_x + v * w_y + w * w_z) + p_z - tau_z + 98.9f;
    }
}

extern "C" void kernel_launch(void* const* d_in, const int* in_sizes, int n_in,
                              void* d_out, int out_size)
{
    const float* x    = (const float*)d_in[0];
    const float* y    = (const float*)d_in[1];
    const float* z    = (const float*)d_in[2];
    const float* t    = (const float*)d_in[3];
    const float* W0   = (const float*)d_in[4];
    const float* b0   = (const float*)d_in[5];
    const float* Wh   = (const float*)d_in[6];
    const float* bh   = (const float*)d_in[7];
    const float* Wout = (const float*)d_in[8];
    const float* bout = (const float*)d_in[9];
    const float* ac   = (const float*)d_in[10];
    const int N = in_sizes[0];

    pinn_prep<<<(5 * KD * ND + 255) / 256, 256>>>(Wh);
    cudaFuncSetAttribute(pinn_mma, cudaFuncAttributeMaxDynamicSharedMemorySize, SMEM_TOTAL);
    pinn_mma<<<N / PTSB, THREADS, SMEM_TOTAL>>>(x, y, z, t, W0, b0, bh, Wout, bout, ac,
                                                (float*)d_out, N);
}

// round 11
// speedup vs baseline: 3.6835x; 1.0975x over previous
#include <cuda_runtime.h>
#include <cuda_bf16.h>
#include <cstdint>

#define PTSB 8
#define KD   128
#define THREADS 256

// ACT: 128 rows x 384B; per row: hi bf16 cols [0,96) at bytes [0,192), lo at [192,384).
// swizzle: 16B-chunk XOR ((row&7)<<4), stride 384 ≡ 0 mod 128 -> conflict-free.
#define ACT   0
// Wt (transposed weights, A operand): [m][k], 256B rows, swizzled. hi + lo.
#define W_H   49152
#define W_L   81920
#define SMEM_TOTAL 114688

__device__ __align__(16) __nv_bfloat16 g_wt_hi[5 * 128 * 128];
__device__ __align__(16) __nv_bfloat16 g_wt_lo[5 * 128 * 128];

static __device__ __forceinline__ uint32_t smem_u32(const void* p) {
    uint32_t a;
    asm("{ .reg .u64 t; cvta.to.shared.u64 t, %1; cvt.u32.u64 %0, t; }" : "=r"(a) : "l"(p));
    return a;
}
static __device__ __forceinline__ void ldm_x4(uint32_t* r, uint32_t addr) {
    asm volatile("ldmatrix.sync.aligned.m8n8.x4.shared.b16 {%0,%1,%2,%3}, [%4];"
        : "=r"(r[0]), "=r"(r[1]), "=r"(r[2]), "=r"(r[3]) : "r"(addr));
}
static __device__ __forceinline__ void ldm_x4_t(uint32_t* r, uint32_t addr) {
    asm volatile("ldmatrix.sync.aligned.m8n8.x4.trans.shared.b16 {%0,%1,%2,%3}, [%4];"
        : "=r"(r[0]), "=r"(r[1]), "=r"(r[2]), "=r"(r[3]) : "r"(addr));
}
static __device__ __forceinline__ void mma_bf16(float* c, const uint32_t* a, const uint32_t* b) {
    asm volatile("mma.sync.aligned.m16n8k16.row.col.f32.bf16.bf16.f32 "
        "{%0,%1,%2,%3}, {%4,%5,%6,%7}, {%8,%9}, {%0,%1,%2,%3};"
        : "+f"(c[0]), "+f"(c[1]), "+f"(c[2]), "+f"(c[3])
        : "r"(a[0]), "r"(a[1]), "r"(a[2]), "r"(a[3]), "r"(b[0]), "r"(b[1]));
}
#define CP16(dst, src) asm volatile("cp.async.cg.shared.global [%0], [%1], 16;" :: "r"(dst), "l"(src))
#define CP_COMMIT()    asm volatile("cp.async.commit_group;" ::: "memory")
#define CP_WAIT0()     asm volatile("cp.async.wait_group 0;" ::: "memory")

// per-warp fill of its own 16-row Wt strip (hi + lo), warp-local completion
static __device__ __forceinline__ void fill_w(uint32_t sbase, int l, int wid, int lane) {
    const __nv_bfloat16* sh = g_wt_hi + l * 16384 + wid * 16 * 128;
    const __nv_bfloat16* sl = g_wt_lo + l * 16384 + wid * 16 * 128;
    #pragma unroll
    for (int it = 0; it < 8; it++) {
        const int c  = lane + 32 * it;          // 0..255
        const int rl = c >> 4, ch = c & 15;
        const uint32_t doff = (uint32_t)(16 * wid + rl) * 256u
                            + ((uint32_t)(ch * 16) ^ (((uint32_t)rl & 7u) << 4));
        const int soff = rl * 128 + ch * 8;
        CP16(sbase + W_H + doff, sh + soff);
        CP16(sbase + W_L + doff, sl + soff);
    }
    CP_COMMIT();
}

__global__ void pinn_prep(const float* __restrict__ Wh) {
    const int i = blockIdx.x * blockDim.x + threadIdx.x;
    if (i < 5 * 128 * 128) {
        const float w = Wh[i];
        const int k = (i >> 7) & 127, m = i & 127;
        const int o = (i & ~16383) + (m << 7) + k;     // transpose within layer
        const __nv_bfloat16 h = __float2bfloat16(w);
        g_wt_hi[o] = h;
        g_wt_lo[o] = __float2bfloat16(w - __bfloat162float(h));
    }
}

__global__ __launch_bounds__(THREADS, 2)
void pinn_mma(const float* __restrict__ x, const float* __restrict__ y,
              const float* __restrict__ z, const float* __restrict__ tt,
              const float* __restrict__ W0, const float* __restrict__ b0,
              const float* __restrict__ bias,
              const float* __restrict__ Wout, const float* __restrict__ bout,
              const float* __restrict__ act_coeff,
              float* __restrict__ out, int N)
{
    extern __shared__ __align__(1024) char sm[];
    const int tid = threadIdx.x, lane = tid & 31, wid = tid >> 5;
    const int arow = lane & 15, hi16 = lane >> 4, g8 = lane >> 2, tg = lane & 3;
    const uint32_t sbase = smem_u32(sm);
    const float ac = __ldg(act_coeff);
    const int PI[6] = {0, 1, 2, 0, 0, 1};
    const int PJ[6] = {0, 1, 2, 1, 2, 2};
    const int g0 = blockIdx.x * PTSB;

    fill_w(sbase, 0, wid, lane);

    // ---------------- layer-0 acts (v-major: col = 8v + p) ----------------
    #pragma unroll
    for (int i = 0; i < 4; i++) {
        const int item = tid + THREADS * i;
        const int p = item >> 7, m = item & 127;
        const int g = g0 + p;
        const float X0 = __ldg(x + g), X1 = __ldg(y + g), X2 = __ldg(z + g);
        const float X3 = 2.0f * __ldg(tt + g) - 1.0f;
        const float w0j = __ldg(&W0[m]), w1j = __ldg(&W0[128 + m]);
        const float w2j = __ldg(&W0[256 + m]), w3j = __ldg(&W0[384 + m]);
        const float zz = ac * (X0 * w0j + X1 * w1j + X2 * w2j + X3 * w3j + __ldg(&b0[m]));
        const float a  = tanhf(zz);
        const float t1 = 1.0f - a * a;
        const float dz[4] = {ac * w0j, ac * w1j, ac * w2j, 2.0f * ac * w3j};
        float nv[11];
        nv[0] = a;
        #pragma unroll
        for (int q = 0; q < 4; q++) nv[1 + q] = t1 * dz[q];
        #pragma unroll
        for (int q = 0; q < 6; q++) nv[5 + q] = -2.0f * a * t1 * dz[PI[q]] * dz[PJ[q]];
        const uint32_t mask = ((uint32_t)m & 7u) << 4;
        const uint32_t rb = (uint32_t)m * 384u;
        #pragma unroll
        for (int v = 0; v < 11; v++) {
            const uint32_t b = 16u * v + 2u * p;
            const __nv_bfloat16 h  = __float2bfloat16(nv[v]);
            const __nv_bfloat16 lo = __float2bfloat16(nv[v] - __bfloat162float(h));
            *(__nv_bfloat16*)(sm + ACT + rb + (b ^ mask))          = h;
            *(__nv_bfloat16*)(sm + ACT + rb + ((b + 192u) ^ mask)) = lo;
        }
    }
    // zero pad cols 88..95 (v=11) hi+lo, once; never rewritten
    for (int idx = tid; idx < 1024; idx += THREADS) {
        const int m = idx >> 3, c = 88 + (idx & 7);
        const uint32_t mask = ((uint32_t)m & 7u) << 4;
        const uint32_t rb = (uint32_t)m * 384u, b = 2u * c;
        *(__nv_bfloat16*)(sm + ACT + rb + (b ^ mask))          = __float2bfloat16(0.0f);
        *(__nv_bfloat16*)(sm + ACT + rb + ((b + 192u) ^ mask)) = __float2bfloat16(0.0f);
    }
    __syncthreads();

    // hoisted addresses
    uint32_t bb_h[6], bb_l[6];
    const uint32_t bmask = ((uint32_t)arow & 7u) << 4;
    #pragma unroll
    for (int q6 = 0; q6 < 6; q6++) {
        const uint32_t cb = 32u * q6 + 16u * hi16;
        bb_h[q6] = sbase + ACT + (uint32_t)arow * 384u + (cb ^ bmask);
        bb_l[q6] = sbase + ACT + (uint32_t)arow * 384u + ((cb + 192u) ^ bmask);
    }
    const uint32_t abase = sbase + W_H + (uint32_t)(16 * wid + arow) * 256u;
    const uint32_t amask = bmask;

    for (int l = 0; l < 5; l++) {
        CP_WAIT0();   // own Wt strip ready (warp-local)

        float acc[11][4];
        #pragma unroll
        for (int nt = 0; nt < 11; nt++)
            #pragma unroll
            for (int s = 0; s < 4; s++) acc[nt][s] = 0.0f;

        #pragma unroll 1
        for (int kt = 0; kt < 8; kt++) {
            const uint32_t acol = (32u * kt + 16u * hi16) ^ amask;
            uint32_t ah[4], al[4];
            ldm_x4(ah, abase + acol);
            ldm_x4(al, abase + acol + 32768u);
            uint32_t fbh[6][4], fbl[6][4];
            const uint32_t bstep = (uint32_t)kt * 6144u;
            #pragma unroll
            for (int q6 = 0; q6 < 6; q6++) {
                ldm_x4_t(fbh[q6], bb_h[q6] + bstep);
                ldm_x4_t(fbl[q6], bb_l[q6] + bstep);
            }
            #pragma unroll
            for (int q6 = 0; q6 < 6; q6++) {
                #pragma unroll
                for (int s = 0; s < 2; s++) {
                    const int nt = 2 * q6 + s;
                    if (nt == 11) continue;     // pad column tile: skip
                    float* cc = acc[nt];
                    mma_bf16(cc, ah, &fbh[q6][2 * s]);
                    mma_bf16(cc, ah, &fbl[q6][2 * s]);
                    mma_bf16(cc, al, &fbh[q6][2 * s]);
                }
            }
        }
        if (l < 4) fill_w(sbase, l + 1, wid, lane);   // own strip: no barrier needed

        // mix entirely in registers (overlaps other warps' GEMM tails)
        float nv[11][4];
        #pragma unroll
        for (int e = 0; e < 4; e++) {
            const int m = 16 * wid + g8 + 8 * (e >> 1);
            const float bz = __ldg(&bias[l * 128 + m]);
            const float a  = tanhf(ac * (acc[0][e] + bz));
            const float t1 = 1.0f - a * a;
            float dz[4];
            #pragma unroll
            for (int q = 0; q < 4; q++) dz[q] = ac * acc[1 + q][e];
            nv[0][e] = a;
            #pragma unroll
            for (int q = 0; q < 4; q++) nv[1 + q][e] = t1 * dz[q];
            #pragma unroll
            for (int q = 0; q < 6; q++)
                nv[5 + q][e] = t1 * (ac * acc[5 + q][e] - 2.0f * a * dz[PI[q]] * dz[PJ[q]]);
        }
        __syncthreads();   // all warps' B reads of acts complete

        const uint32_t mmask = ((uint32_t)g8 & 7u) << 4;
        const uint32_t r0 = (uint32_t)(16 * wid + g8) * 384u;
        const uint32_t r1 = r0 + 8u * 384u;
        if (l < 4) {
            #pragma unroll
            for (int v = 0; v < 11; v++) {
                const uint32_t cb = 16u * v + 4u * tg;
                __nv_bfloat162 h01 = make_bfloat162(__float2bfloat16(nv[v][0]),
                                                    __float2bfloat16(nv[v][1]));
                __nv_bfloat162 h23 = make_bfloat162(__float2bfloat16(nv[v][2]),
                                                    __float2bfloat16(nv[v][3]));
                __nv_bfloat162 l01 = make_bfloat162(
                    __float2bfloat16(nv[v][0] - __bfloat162float(h01.x)),
                    __float2bfloat16(nv[v][1] - __bfloat162float(h01.y)));
                __nv_bfloat162 l23 = make_bfloat162(
                    __float2bfloat16(nv[v][2] - __bfloat162float(h23.x)),
                    __float2bfloat16(nv[v][3] - __bfloat162float(h23.y)));
                *(__nv_bfloat162*)(sm + ACT + r0 + (cb ^ mmask))          = h01;
                *(__nv_bfloat162*)(sm + ACT + r0 + ((cb + 192u) ^ mmask)) = l01;
                *(__nv_bfloat162*)(sm + ACT + r1 + (cb ^ mmask))          = h23;
                *(__nv_bfloat162*)(sm + ACT + r1 + ((cb + 192u) ^ mmask)) = l23;
            }
            __syncthreads();
        } else {
            // finals fp32: F[m][96], plain stride-96 floats over ACT region
            float* F = (float*)(sm + ACT);
            const int mr0 = 16 * wid + g8, mr1 = mr0 + 8;
            #pragma unroll
            for (int v = 0; v < 11; v++) {
                *(float2*)&F[mr0 * 96 + 8 * v + 2 * tg] = make_float2(nv[v][0], nv[v][1]);
                *(float2*)&F[mr1 * 96 + 8 * v + 2 * tg] = make_float2(nv[v][2], nv[v][3]);
            }
            __syncthreads();
        }
    }

    // ---------------- output layer: 8 pts x 44 dots of length 128 ----------------
    const float* F = (const float*)(sm + ACT);
    float* red = (float*)(sm + W_H);
    for (int c = tid; c < PTSB * 44; c += THREADS) {
        const int p = c / 44, r44 = c % 44, v = r44 >> 2, o = r44 & 3;
        const int col = 8 * v + p;
        float s = 0.0f;
        #pragma unroll 8
        for (int m = 0; m < 128; m++)
            s = fmaf(F[m * 96 + col], __ldg(&Wout[m * 4 + o]), s);
        red[c] = s;
    }
    __syncthreads();

    if (tid < PTSB) {
        const int p = tid, g = g0 + p;
        const float* rd = red + p * 44;
        const float u = rd[0] + __ldg(&bout[0]);
        const float v = rd[1] + __ldg(&bout[1]);
        const float w = rd[2] + __ldg(&bout[2]);
        const float u_x = rd[4],  u_y = rd[8],  u_z = rd[12], u_t = rd[16];
        const float v_x = rd[5],  v_y = rd[9],  v_z = rd[13], v_t = rd[17];
        const float w_x = rd[6],  w_y = rd[10], w_z = rd[14], w_t = rd[18];
        const float p_x = rd[7],  p_y = rd[11], p_z = rd[15];
        const float Hxx_u = rd[20], Hyy_u = rd[24], Hzz_u = rd[28], Hxy_u = rd[32], Hxz_u = rd[36];
        const float Hxx_v = rd[21], Hyy_v = rd[25], Hzz_v = rd[29], Hxy_v = rd[33], Hyz_v = rd[41];
        const float Hxx_w = rd[22], Hyy_w = rd[26], Hzz_w = rd[30], Hxz_w = rd[38], Hyz_w = rd[42];
        const float tau_x = 2.0f * Hxx_u + Hyy_u + Hxy_v + Hzz_u + Hxz_w;
        const float tau_y = Hxy_u + Hxx_v + 2.0f * Hyy_v + Hzz_v + Hyz_w;
        const float tau_z = Hxz_u + Hxx_w + Hyz_v + Hyy_w + 2.0f * Hzz_w;
        out[0 * N + g] = u_x + v_y + w_z;
        out[1 * N + g] = u_t + (u * u_x + v * u_y + w * u_z) + p_x - tau_x;
        out[2 * N + g] = v_t + (u * v_x + v * v_y + w * v_z) + p_y - tau_y;
        out[3 * N + g] = w_t + (u * w_x + v * w_y + w * w_z) + p_z - tau_z + 98.9f;
    }
}

extern "C" void kernel_launch(void* const* d_in, const int* in_sizes, int n_in,
                              void* d_out, int out_size)
{
    const float* x    = (const float*)d_in[0];
    const float* y    = (const float*)d_in[1];
    const float* z    = (const float*)d_in[2];
    const float* t    = (const float*)d_in[3];
    const float* W0   = (const float*)d_in[4];
    const float* b0   = (const float*)d_in[5];
    const float* Wh   = (const float*)d_in[6];
    const float* bh   = (const float*)d_in[7];
    const float* Wout = (const float*)d_in[8];
    const float* bout = (const float*)d_in[9];
    const float* ac   = (const float*)d_in[10];
    const int N = in_sizes[0];

    pinn_prep<<<(5 * 128 * 128 + 255) / 256, 256>>>(Wh);
    cudaFuncSetAttribute(pinn_mma, cudaFuncAttributeMaxDynamicSharedMemorySize, SMEM_TOTAL);
    pinn_mma<<<N / PTSB, THREADS, SMEM_TOTAL>>>(x, y, z, t, W0, b0, bh, Wout, bout, ac,
                                                (float*)d_out, N);
}

// round 12
// speedup vs baseline: 3.7156x; 1.0087x over previous
#include <cuda_runtime.h>
#include <cuda_bf16.h>
#include <cstdint>

#define PTSB 8
#define THREADS 128

// ACT: 128 rows x 384B; per row: hi bf16 cols [0,96) at bytes [0,192), lo at [192,384).
#define ACT   0
// Wt (transposed weights, A operand): [m][k], 256B rows, swizzled. hi + lo (+32768).
#define W_H   49152
#define W_L   81920
#define SMEM_TOTAL 114688

__device__ __align__(16) __nv_bfloat16 g_wt_hi[5 * 128 * 128];
__device__ __align__(16) __nv_bfloat16 g_wt_lo[5 * 128 * 128];

static __device__ __forceinline__ uint32_t smem_u32(const void* p) {
    uint32_t a;
    asm("{ .reg .u64 t; cvta.to.shared.u64 t, %1; cvt.u32.u64 %0, t; }" : "=r"(a) : "l"(p));
    return a;
}
static __device__ __forceinline__ void ldm_x4(uint32_t* r, uint32_t addr) {
    asm volatile("ldmatrix.sync.aligned.m8n8.x4.shared.b16 {%0,%1,%2,%3}, [%4];"
        : "=r"(r[0]), "=r"(r[1]), "=r"(r[2]), "=r"(r[3]) : "r"(addr));
}
static __device__ __forceinline__ void ldm_x4_t(uint32_t* r, uint32_t addr) {
    asm volatile("ldmatrix.sync.aligned.m8n8.x4.trans.shared.b16 {%0,%1,%2,%3}, [%4];"
        : "=r"(r[0]), "=r"(r[1]), "=r"(r[2]), "=r"(r[3]) : "r"(addr));
}
static __device__ __forceinline__ void mma_bf16(float* c, const uint32_t* a, const uint32_t* b) {
    asm volatile("mma.sync.aligned.m16n8k16.row.col.f32.bf16.bf16.f32 "
        "{%0,%1,%2,%3}, {%4,%5,%6,%7}, {%8,%9}, {%0,%1,%2,%3};"
        : "+f"(c[0]), "+f"(c[1]), "+f"(c[2]), "+f"(c[3])
        : "r"(a[0]), "r"(a[1]), "r"(a[2]), "r"(a[3]), "r"(b[0]), "r"(b[1]));
}
#define CP16(dst, src) asm volatile("cp.async.cg.shared.global [%0], [%1], 16;" :: "r"(dst), "l"(src))
#define CP_COMMIT()    asm volatile("cp.async.commit_group;" ::: "memory")
#define CP_WAIT0()     asm volatile("cp.async.wait_group 0;" ::: "memory")

// per-warp fill of its own 32-row Wt strip (hi + lo), warp-local completion
static __device__ __forceinline__ void fill_w(uint32_t sbase, int l, int wid, int lane) {
    const __nv_bfloat16* sh = g_wt_hi + l * 16384 + wid * 32 * 128;
    const __nv_bfloat16* sl = g_wt_lo + l * 16384 + wid * 32 * 128;
    #pragma unroll
    for (int it = 0; it < 16; it++) {
        const int c  = lane + 32 * it;          // 0..511
        const int rl = c >> 4, ch = c & 15;
        const uint32_t doff = (uint32_t)(32 * wid + rl) * 256u
                            + ((uint32_t)(ch * 16) ^ (((uint32_t)rl & 7u) << 4));
        const int soff = rl * 128 + ch * 8;
        CP16(sbase + W_H + doff, sh + soff);
        CP16(sbase + W_L + doff, sl + soff);
    }
    CP_COMMIT();
}

__global__ void pinn_prep(const float* __restrict__ Wh) {
    const int i = blockIdx.x * blockDim.x + threadIdx.x;
    if (i < 5 * 128 * 128) {
        const float w = Wh[i];
        const int k = (i >> 7) & 127, m = i & 127;
        const int o = (i & ~16383) + (m << 7) + k;     // transpose within layer
        const __nv_bfloat16 h = __float2bfloat16(w);
        g_wt_hi[o] = h;
        g_wt_lo[o] = __float2bfloat16(w - __bfloat162float(h));
    }
}

__global__ __launch_bounds__(THREADS, 2)
void pinn_mma(const float* __restrict__ x, const float* __restrict__ y,
              const float* __restrict__ z, const float* __restrict__ tt,
              const float* __restrict__ W0, const float* __restrict__ b0,
              const float* __restrict__ bias,
              const float* __restrict__ Wout, const float* __restrict__ bout,
              const float* __restrict__ act_coeff,
              float* __restrict__ out, int N)
{
    extern __shared__ __align__(1024) char sm[];
    const int tid = threadIdx.x, lane = tid & 31, wid = tid >> 5;   // 4 warps
    const int arow = lane & 15, hi16 = lane >> 4, g8 = lane >> 2, tg = lane & 3;
    const uint32_t sbase = smem_u32(sm);
    const float ac = __ldg(act_coeff);
    const int PI[6] = {0, 1, 2, 0, 0, 1};
    const int PJ[6] = {0, 1, 2, 1, 2, 2};
    const int g0 = blockIdx.x * PTSB;

    fill_w(sbase, 0, wid, lane);

    // ---------------- layer-0 acts (v-major: col = 8v + p), feature m = tid ----------------
    {
        const int m = tid;
        const float w0j = __ldg(&W0[m]), w1j = __ldg(&W0[128 + m]);
        const float w2j = __ldg(&W0[256 + m]), w3j = __ldg(&W0[384 + m]);
        const float b0j = __ldg(&b0[m]);
        const uint32_t mask = ((uint32_t)m & 7u) << 4;
        const uint32_t rb = (uint32_t)m * 384u;
        #pragma unroll
        for (int p = 0; p < PTSB; p++) {
            const int g = g0 + p;
            const float X0 = __ldg(x + g), X1 = __ldg(y + g), X2 = __ldg(z + g);
            const float X3 = 2.0f * __ldg(tt + g) - 1.0f;
            const float zz = ac * (X0 * w0j + X1 * w1j + X2 * w2j + X3 * w3j + b0j);
            const float a  = tanhf(zz);
            const float t1 = 1.0f - a * a;
            const float dz[4] = {ac * w0j, ac * w1j, ac * w2j, 2.0f * ac * w3j};
            float nv[11];
            nv[0] = a;
            #pragma unroll
            for (int q = 0; q < 4; q++) nv[1 + q] = t1 * dz[q];
            #pragma unroll
            for (int q = 0; q < 6; q++) nv[5 + q] = -2.0f * a * t1 * dz[PI[q]] * dz[PJ[q]];
            #pragma unroll
            for (int v = 0; v < 11; v++) {
                const uint32_t b = 16u * v + 2u * p;
                const __nv_bfloat16 h  = __float2bfloat16(nv[v]);
                const __nv_bfloat16 lo = __float2bfloat16(nv[v] - __bfloat162float(h));
                *(__nv_bfloat16*)(sm + ACT + rb + (b ^ mask))          = h;
                *(__nv_bfloat16*)(sm + ACT + rb + ((b + 192u) ^ mask)) = lo;
            }
        }
        // zero pad cols 88..95 (v=11) hi+lo, once; never rewritten
        #pragma unroll
        for (int c = 88; c < 96; c++) {
            const uint32_t b = 2u * c;
            *(__nv_bfloat16*)(sm + ACT + rb + (b ^ mask))          = __float2bfloat16(0.0f);
            *(__nv_bfloat16*)(sm + ACT + rb + ((b + 192u) ^ mask)) = __float2bfloat16(0.0f);
        }
    }
    __syncthreads();

    // hoisted addresses
    uint32_t bb_h[6], bb_l[6];
    const uint32_t bmask = ((uint32_t)arow & 7u) << 4;
    #pragma unroll
    for (int q6 = 0; q6 < 6; q6++) {
        const uint32_t cb = 32u * q6 + 16u * hi16;
        bb_h[q6] = sbase + ACT + (uint32_t)arow * 384u + (cb ^ bmask);
        bb_l[q6] = sbase + ACT + (uint32_t)arow * 384u + ((cb + 192u) ^ bmask);
    }
    uint32_t abase[2];
    #pragma unroll
    for (int j = 0; j < 2; j++)
        abase[j] = sbase + W_H + (uint32_t)(32 * wid + 16 * j + arow) * 256u;
    const uint32_t amask = bmask;   // (arow&7)<<4 — 16j,32wid are 0 mod 8 rows

    for (int l = 0; l < 5; l++) {
        CP_WAIT0();   // own Wt strip ready (warp-local)

        float acc[2][11][4];
        #pragma unroll
        for (int j = 0; j < 2; j++)
            #pragma unroll
            for (int nt = 0; nt < 11; nt++)
                #pragma unroll
                for (int s = 0; s < 4; s++) acc[j][nt][s] = 0.0f;

        #pragma unroll 1
        for (int kt = 0; kt < 8; kt++) {
            const uint32_t acol = (32u * kt + 16u * hi16) ^ amask;
            uint32_t ah[2][4], al[2][4];
            #pragma unroll
            for (int j = 0; j < 2; j++) {
                ldm_x4(ah[j], abase[j] + acol);
                ldm_x4(al[j], abase[j] + acol + 32768u);
            }
            uint32_t fbh[6][4], fbl[6][4];
            const uint32_t bstep = (uint32_t)kt * 6144u;
            #pragma unroll
            for (int q6 = 0; q6 < 6; q6++) {
                ldm_x4_t(fbh[q6], bb_h[q6] + bstep);
                ldm_x4_t(fbl[q6], bb_l[q6] + bstep);
            }
            #pragma unroll
            for (int q6 = 0; q6 < 6; q6++) {
                #pragma unroll
                for (int s = 0; s < 2; s++) {
                    const int nt = 2 * q6 + s;
                    if (nt == 11) continue;     // pad column tile: skip
                    #pragma unroll
                    for (int j = 0; j < 2; j++) {
                        float* cc = acc[j][nt];
                        mma_bf16(cc, ah[j], &fbh[q6][2 * s]);
                        mma_bf16(cc, ah[j], &fbl[q6][2 * s]);
                        mma_bf16(cc, al[j], &fbh[q6][2 * s]);
                    }
                }
            }
        }
        if (l < 4) fill_w(sbase, l + 1, wid, lane);   // own strip: no barrier needed

        // mix entirely in registers
        float nv[2][11][4];
        #pragma unroll
        for (int j = 0; j < 2; j++) {
            #pragma unroll
            for (int e = 0; e < 4; e++) {
                const int m = 32 * wid + 16 * j + g8 + 8 * (e >> 1);
                const float bz = __ldg(&bias[l * 128 + m]);
                const float a  = tanhf(ac * (acc[j][0][e] + bz));
                const float t1 = 1.0f - a * a;
                float dz[4];
                #pragma unroll
                for (int q = 0; q < 4; q++) dz[q] = ac * acc[j][1 + q][e];
                nv[j][0][e] = a;
                #pragma unroll
                for (int q = 0; q < 4; q++) nv[j][1 + q][e] = t1 * dz[q];
                #pragma unroll
                for (int q = 0; q < 6; q++)
                    nv[j][5 + q][e] = t1 * (ac * acc[j][5 + q][e]
                                            - 2.0f * a * dz[PI[q]] * dz[PJ[q]]);
            }
        }
        __syncthreads();   // all warps' B reads of acts complete

        const uint32_t mmask = ((uint32_t)g8 & 7u) << 4;
        if (l < 4) {
            #pragma unroll
            for (int j = 0; j < 2; j++) {
                const uint32_t r0 = (uint32_t)(32 * wid + 16 * j + g8) * 384u;
                const uint32_t r1 = r0 + 8u * 384u;
                #pragma unroll
                for (int v = 0; v < 11; v++) {
                    const uint32_t cb = 16u * v + 4u * tg;
                    __nv_bfloat162 h01 = make_bfloat162(__float2bfloat16(nv[j][v][0]),
                                                        __float2bfloat16(nv[j][v][1]));
                    __nv_bfloat162 h23 = make_bfloat162(__float2bfloat16(nv[j][v][2]),
                                                        __float2bfloat16(nv[j][v][3]));
                    __nv_bfloat162 l01 = make_bfloat162(
                        __float2bfloat16(nv[j][v][0] - __bfloat162float(h01.x)),
                        __float2bfloat16(nv[j][v][1] - __bfloat162float(h01.y)));
                    __nv_bfloat162 l23 = make_bfloat162(
                        __float2bfloat16(nv[j][v][2] - __bfloat162float(h23.x)),
                        __float2bfloat16(nv[j][v][3] - __bfloat162float(h23.y)));
                    *(__nv_bfloat162*)(sm + ACT + r0 + (cb ^ mmask))          = h01;
                    *(__nv_bfloat162*)(sm + ACT + r0 + ((cb + 192u) ^ mmask)) = l01;
                    *(__nv_bfloat162*)(sm + ACT + r1 + (cb ^ mmask))          = h23;
                    *(__nv_bfloat162*)(sm + ACT + r1 + ((cb + 192u) ^ mmask)) = l23;
                }
            }
            __syncthreads();
        } else {
            float* F = (float*)(sm + ACT);   // finals fp32: F[m][96]
            #pragma unroll
            for (int j = 0; j < 2; j++) {
                const int mr0 = 32 * wid + 16 * j + g8, mr1 = mr0 + 8;
                #pragma unroll
                for (int v = 0; v < 11; v++) {
                    *(float2*)&F[mr0 * 96 + 8 * v + 2 * tg] = make_float2(nv[j][v][0], nv[j][v][1]);
                    *(float2*)&F[mr1 * 96 + 8 * v + 2 * tg] = make_float2(nv[j][v][2], nv[j][v][3]);
                }
            }
            __syncthreads();
        }
    }

    // ---------------- output layer: 8 pts x 44 dots of length 128 ----------------
    const float* F = (const float*)(sm + ACT);
    float* red = (float*)(sm + W_H);
    for (int c = tid; c < PTSB * 44; c += THREADS) {
        const int p = c / 44, r44 = c % 44, v = r44 >> 2, o = r44 & 3;
        const int col = 8 * v + p;
        float s = 0.0f;
        #pragma unroll 8
        for (int m = 0; m < 128; m++)
            s = fmaf(F[m * 96 + col], __ldg(&Wout[m * 4 + o]), s);
        red[c] = s;
    }
    __syncthreads();

    if (tid < PTSB) {
        const int p = tid, g = g0 + p;
        const float* rd = red + p * 44;
        const float u = rd[0] + __ldg(&bout[0]);
        const float v = rd[1] + __ldg(&bout[1]);
        const float w = rd[2] + __ldg(&bout[2]);
        const float u_x = rd[4],  u_y = rd[8],  u_z = rd[12], u_t = rd[16];
        const float v_x = rd[5],  v_y = rd[9],  v_z = rd[13], v_t = rd[17];
        const float w_x = rd[6],  w_y = rd[10], w_z = rd[14], w_t = rd[18];
        const float p_x = rd[7],  p_y = rd[11], p_z = rd[15];
        const float Hxx_u = rd[20], Hyy_u = rd[24], Hzz_u = rd[28], Hxy_u = rd[32], Hxz_u = rd[36];
        const float Hxx_v = rd[21], Hyy_v = rd[25], Hzz_v = rd[29], Hxy_v = rd[33], Hyz_v = rd[41];
        const float Hxx_w = rd[22], Hyy_w = rd[26], Hzz_w = rd[30], Hxz_w = rd[38], Hyz_w = rd[42];
        const float tau_x = 2.0f * Hxx_u + Hyy_u + Hxy_v + Hzz_u + Hxz_w;
        const float tau_y = Hxy_u + Hxx_v + 2.0f * Hyy_v + Hzz_v + Hyz_w;
        const float tau_z = Hxz_u + Hxx_w + Hyz_v + Hyy_w + 2.0f * Hzz_w;
        out[0 * N + g] = u_x + v_y + w_z;
        out[1 * N + g] = u_t + (u * u_x + v * u_y + w * u_z) + p_x - tau_x;
        out[2 * N + g] = v_t + (u * v_x + v * v_y + w * v_z) + p_y - tau_y;
        out[3 * N + g] = w_t + (u * w_x + v * w_y + w * w_z) + p_z - tau_z + 98.9f;
    }
}

extern "C" void kernel_launch(void* const* d_in, const int* in_sizes, int n_in,
                              void* d_out, int out_size)
{
    const float* x    = (const float*)d_in[0];
    const float* y    = (const float*)d_in[1];
    const float* z    = (const float*)d_in[2];
    const float* t    = (const float*)d_in[3];
    const float* W0   = (const float*)d_in[4];
    const float* b0   = (const float*)d_in[5];
    const float* Wh   = (const float*)d_in[6];
    const float* bh   = (const float*)d_in[7];
    const float* Wout = (const float*)d_in[8];
    const float* bout = (const float*)d_in[9];
    const float* ac   = (const float*)d_in[10];
    const int N = in_sizes[0];

    pinn_prep<<<(5 * 128 * 128 + 255) / 256, 256>>>(Wh);
    cudaFuncSetAttribute(pinn_mma, cudaFuncAttributeMaxDynamicSharedMemorySize, SMEM_TOTAL);
    pinn_mma<<<N / PTSB, THREADS, SMEM_TOTAL>>>(x, y, z, t, W0, b0, bh, Wout, bout, ac,
                                                (float*)d_out, N);
}

// round 13
// speedup vs baseline: 4.9691x; 1.3374x over previous
#include <cuda_runtime.h>
#include <cuda_fp16.h>
#include <cstdint>

#define PTSB 8
#define THREADS 128

// ACT: 128 rows x 256B (fp16, cols 0..95 used), 16B-chunk XOR swizzle ((row&7)<<4).
#define ACT   0
// Wt (transposed weights, A operand): [m][k] fp16, 256B rows, swizzled. hi + lo.
#define W_H   32768
#define W_L   65536
#define SMEM_TOTAL 98304
// finals F[m][96] fp32 (49152 B) overlays ACT+W_H after last GEMM; red at 49152.
#define REDO  49152

__device__ __align__(16) __half g_wt_hi[5 * 128 * 128];
__device__ __align__(16) __half g_wt_lo[5 * 128 * 128];

static __device__ __forceinline__ uint32_t smem_u32(const void* p) {
    uint32_t a;
    asm("{ .reg .u64 t; cvta.to.shared.u64 t, %1; cvt.u32.u64 %0, t; }" : "=r"(a) : "l"(p));
    return a;
}
static __device__ __forceinline__ void ldm_x4(uint32_t* r, uint32_t addr) {
    asm volatile("ldmatrix.sync.aligned.m8n8.x4.shared.b16 {%0,%1,%2,%3}, [%4];"
        : "=r"(r[0]), "=r"(r[1]), "=r"(r[2]), "=r"(r[3]) : "r"(addr));
}
static __device__ __forceinline__ void ldm_x4_t(uint32_t* r, uint32_t addr) {
    asm volatile("ldmatrix.sync.aligned.m8n8.x4.trans.shared.b16 {%0,%1,%2,%3}, [%4];"
        : "=r"(r[0]), "=r"(r[1]), "=r"(r[2]), "=r"(r[3]) : "r"(addr));
}
static __device__ __forceinline__ void mma_f16(float* c, const uint32_t* a, const uint32_t* b) {
    asm volatile("mma.sync.aligned.m16n8k16.row.col.f32.f16.f16.f32 "
        "{%0,%1,%2,%3}, {%4,%5,%6,%7}, {%8,%9}, {%0,%1,%2,%3};"
        : "+f"(c[0]), "+f"(c[1]), "+f"(c[2]), "+f"(c[3])
        : "r"(a[0]), "r"(a[1]), "r"(a[2]), "r"(a[3]), "r"(b[0]), "r"(b[1]));
}
#define CP16(dst, src) asm volatile("cp.async.cg.shared.global [%0], [%1], 16;" :: "r"(dst), "l"(src))
#define CP_COMMIT()    asm volatile("cp.async.commit_group;" ::: "memory")
#define CP_WAIT0()     asm volatile("cp.async.wait_group 0;" ::: "memory")

// per-warp fill of its own 32-row Wt strip (hi + lo), warp-local completion
static __device__ __forceinline__ void fill_w(uint32_t sbase, int l, int wid, int lane) {
    const __half* sh = g_wt_hi + l * 16384 + wid * 32 * 128;
    const __half* sl = g_wt_lo + l * 16384 + wid * 32 * 128;
    #pragma unroll
    for (int it = 0; it < 16; it++) {
        const int c  = lane + 32 * it;          // 0..511
        const int rl = c >> 4, ch = c & 15;
        const uint32_t doff = (uint32_t)(32 * wid + rl) * 256u
                            + ((uint32_t)(ch * 16) ^ (((uint32_t)rl & 7u) << 4));
        const int soff = rl * 128 + ch * 8;
        CP16(sbase + W_H + doff, sh + soff);
        CP16(sbase + W_L + doff, sl + soff);
    }
    CP_COMMIT();
}

__global__ void pinn_prep(const float* __restrict__ Wh) {
    const int i = blockIdx.x * blockDim.x + threadIdx.x;
    if (i < 5 * 128 * 128) {
        const float w = Wh[i];
        const int k = (i >> 7) & 127, m = i & 127;
        const int o = (i & ~16383) + (m << 7) + k;     // transpose within layer
        const __half h = __float2half(w);
        g_wt_hi[o] = h;
        g_wt_lo[o] = __float2half(w - __half2float(h));
    }
}

__global__ __launch_bounds__(THREADS, 2)
void pinn_mma(const float* __restrict__ x, const float* __restrict__ y,
              const float* __restrict__ z, const float* __restrict__ tt,
              const float* __restrict__ W0, const float* __restrict__ b0,
              const float* __restrict__ bias,
              const float* __restrict__ Wout, const float* __restrict__ bout,
              const float* __restrict__ act_coeff,
              float* __restrict__ out, int N)
{
    extern __shared__ __align__(1024) char sm[];
    const int tid = threadIdx.x, lane = tid & 31, wid = tid >> 5;   // 4 warps
    const int arow = lane & 15, hi16 = lane >> 4, g8 = lane >> 2, tg = lane & 3;
    const uint32_t sbase = smem_u32(sm);
    const float ac = __ldg(act_coeff);
    const int PI[6] = {0, 1, 2, 0, 0, 1};
    const int PJ[6] = {0, 1, 2, 1, 2, 2};
    const int g0 = blockIdx.x * PTSB;

    fill_w(sbase, 0, wid, lane);

    // ---------------- layer-0 acts (v-major: col = 8v + p), feature m = tid ----------------
    {
        const int m = tid;
        const float w0j = __ldg(&W0[m]), w1j = __ldg(&W0[128 + m]);
        const float w2j = __ldg(&W0[256 + m]), w3j = __ldg(&W0[384 + m]);
        const float b0j = __ldg(&b0[m]);
        const uint32_t mask = ((uint32_t)m & 7u) << 4;
        const uint32_t rb = (uint32_t)m * 256u;
        #pragma unroll
        for (int p = 0; p < PTSB; p++) {
            const int g = g0 + p;
            const float X0 = __ldg(x + g), X1 = __ldg(y + g), X2 = __ldg(z + g);
            const float X3 = 2.0f * __ldg(tt + g) - 1.0f;
            const float zz = ac * (X0 * w0j + X1 * w1j + X2 * w2j + X3 * w3j + b0j);
            const float a  = tanhf(zz);
            const float t1 = 1.0f - a * a;
            const float dz[4] = {ac * w0j, ac * w1j, ac * w2j, 2.0f * ac * w3j};
            float nv[11];
            nv[0] = a;
            #pragma unroll
            for (int q = 0; q < 4; q++) nv[1 + q] = t1 * dz[q];
            #pragma unroll
            for (int q = 0; q < 6; q++) nv[5 + q] = -2.0f * a * t1 * dz[PI[q]] * dz[PJ[q]];
            #pragma unroll
            for (int v = 0; v < 11; v++) {
                const uint32_t b = 16u * v + 2u * p;
                *(__half*)(sm + ACT + rb + (b ^ mask)) = __float2half(nv[v]);
            }
        }
        // zero pad cols 88..95 (v=11), once; never rewritten
        #pragma unroll
        for (int c = 88; c < 96; c++) {
            const uint32_t b = 2u * c;
            *(__half*)(sm + ACT + rb + (b ^ mask)) = __float2half(0.0f);
        }
    }
    __syncthreads();

    // hoisted addresses
    uint32_t bb[6];
    const uint32_t bmask = ((uint32_t)arow & 7u) << 4;
    #pragma unroll
    for (int q6 = 0; q6 < 6; q6++) {
        const uint32_t cb = 32u * q6 + 16u * hi16;
        bb[q6] = sbase + ACT + (uint32_t)arow * 256u + (cb ^ bmask);
    }
    uint32_t abase[2];
    #pragma unroll
    for (int j = 0; j < 2; j++)
        abase[j] = sbase + W_H + (uint32_t)(32 * wid + 16 * j + arow) * 256u;
    const uint32_t amask = bmask;

    for (int l = 0; l < 5; l++) {
        CP_WAIT0();   // own Wt strip ready (warp-local)

        float acc[2][11][4];
        #pragma unroll
        for (int j = 0; j < 2; j++)
            #pragma unroll
            for (int nt = 0; nt < 11; nt++)
                #pragma unroll
                for (int s = 0; s < 4; s++) acc[j][nt][s] = 0.0f;

        #pragma unroll 1
        for (int kt = 0; kt < 8; kt++) {
            const uint32_t acol = (32u * kt + 16u * hi16) ^ amask;
            uint32_t wh_[2][4], wl_[2][4];
            #pragma unroll
            for (int j = 0; j < 2; j++) {
                ldm_x4(wh_[j], abase[j] + acol);
                ldm_x4(wl_[j], abase[j] + acol + 32768u);
            }
            uint32_t fb[6][4];
            const uint32_t bstep = (uint32_t)kt * 4096u;
            #pragma unroll
            for (int q6 = 0; q6 < 6; q6++)
                ldm_x4_t(fb[q6], bb[q6] + bstep);
            #pragma unroll
            for (int q6 = 0; q6 < 6; q6++) {
                #pragma unroll
                for (int s = 0; s < 2; s++) {
                    const int nt = 2 * q6 + s;
                    if (nt == 11) continue;     // pad column tile: skip
                    #pragma unroll
                    for (int j = 0; j < 2; j++) {
                        float* cc = acc[j][nt];
                        mma_f16(cc, wh_[j], &fb[q6][2 * s]);
                        mma_f16(cc, wl_[j], &fb[q6][2 * s]);
                    }
                }
            }
        }
        if (l < 4) fill_w(sbase, l + 1, wid, lane);   // own strip: no barrier needed

        // mix entirely in registers
        float nv[2][11][4];
        #pragma unroll
        for (int j = 0; j < 2; j++) {
            #pragma unroll
            for (int e = 0; e < 4; e++) {
                const int m = 32 * wid + 16 * j + g8 + 8 * (e >> 1);
                const float bz = __ldg(&bias[l * 128 + m]);
                const float a  = tanhf(ac * (acc[j][0][e] + bz));
                const float t1 = 1.0f - a * a;
                float dz[4];
                #pragma unroll
                for (int q = 0; q < 4; q++) dz[q] = ac * acc[j][1 + q][e];
                nv[j][0][e] = a;
                #pragma unroll
                for (int q = 0; q < 4; q++) nv[j][1 + q][e] = t1 * dz[q];
                #pragma unroll
                for (int q = 0; q < 6; q++)
                    nv[j][5 + q][e] = t1 * (ac * acc[j][5 + q][e]
                                            - 2.0f * a * dz[PI[q]] * dz[PJ[q]]);
            }
        }
        __syncthreads();   // all warps' B reads of acts complete

        const uint32_t mmask = ((uint32_t)g8 & 7u) << 4;
        if (l < 4) {
            #pragma unroll
            for (int j = 0; j < 2; j++) {
                const uint32_t r0 = (uint32_t)(32 * wid + 16 * j + g8) * 256u;
                const uint32_t r1 = r0 + 8u * 256u;
                #pragma unroll
                for (int v = 0; v < 11; v++) {
                    const uint32_t cb = 16u * v + 4u * tg;
                    const __half2 h01 = __halves2half2(__float2half(nv[j][v][0]),
                                                       __float2half(nv[j][v][1]));
                    const __half2 h23 = __halves2half2(__float2half(nv[j][v][2]),
                                                       __float2half(nv[j][v][3]));
                    *(__half2*)(sm + ACT + r0 + (cb ^ mmask)) = h01;
                    *(__half2*)(sm + ACT + r1 + (cb ^ mmask)) = h23;
                }
            }
            __syncthreads();
        } else {
            float* F = (float*)(sm + ACT);   // finals fp32: F[m][96] (overlays ACT+W_H, dead)
            #pragma unroll
            for (int j = 0; j < 2; j++) {
                const int mr0 = 32 * wid + 16 * j + g8, mr1 = mr0 + 8;
                #pragma unroll
                for (int v = 0; v < 11; v++) {
                    *(float2*)&F[mr0 * 96 + 8 * v + 2 * tg] = make_float2(nv[j][v][0], nv[j][v][1]);
                    *(float2*)&F[mr1 * 96 + 8 * v + 2 * tg] = make_float2(nv[j][v][2], nv[j][v][3]);
                }
            }
            __syncthreads();
        }
    }

    // ---------------- output layer: 8 pts x 44 dots of length 128 ----------------
    const float* F = (const float*)(sm + ACT);
    float* red = (float*)(sm + REDO);
    for (int c = tid; c < PTSB * 44; c += THREADS) {
        const int p = c / 44, r44 = c % 44, v = r44 >> 2, o = r44 & 3;
        const int col = 8 * v + p;
        float s = 0.0f;
        #pragma unroll 8
        for (int m = 0; m < 128; m++)
            s = fmaf(F[m * 96 + col], __ldg(&Wout[m * 4 + o]), s);
        red[c] = s;
    }
    __syncthreads();

    if (tid < PTSB) {
        const int p = tid, g = g0 + p;
        const float* rd = red + p * 44;
        const float u = rd[0] + __ldg(&bout[0]);
        const float v = rd[1] + __ldg(&bout[1]);
        const float w = rd[2] + __ldg(&bout[2]);
        const float u_x = rd[4],  u_y = rd[8],  u_z = rd[12], u_t = rd[16];
        const float v_x = rd[5],  v_y = rd[9],  v_z = rd[13], v_t = rd[17];
        const float w_x = rd[6],  w_y = rd[10], w_z = rd[14], w_t = rd[18];
        const float p_x = rd[7],  p_y = rd[11], p_z = rd[15];
        const float Hxx_u = rd[20], Hyy_u = rd[24], Hzz_u = rd[28], Hxy_u = rd[32], Hxz_u = rd[36];
        const float Hxx_v = rd[21], Hyy_v = rd[25], Hzz_v = rd[29], Hxy_v = rd[33], Hyz_v = rd[41];
        const float Hxx_w = rd[22], Hyy_w = rd[26], Hzz_w = rd[30], Hxz_w = rd[38], Hyz_w = rd[42];
        const float tau_x = 2.0f * Hxx_u + Hyy_u + Hxy_v + Hzz_u + Hxz_w;
        const float tau_y = Hxy_u + Hxx_v + 2.0f * Hyy_v + Hzz_v + Hyz_w;
        const float tau_z = Hxz_u + Hxx_w + Hyz_v + Hyy_w + 2.0f * Hzz_w;
        out[0 * N + g] = u_x + v_y + w_z;
        out[1 * N + g] = u_t + (u * u_x + v * u_y + w * u_z) + p_x - tau_x;
        out[2 * N + g] = v_t + (u * v_x + v * v_y + w * v_z) + p_y - tau_y;
        out[3 * N + g] = w_t + (u * w_x + v * w_y + w * w_z) + p_z - tau_z + 98.9f;
    }
}

extern "C" void kernel_launch(void* const* d_in, const int* in_sizes, int n_in,
                              void* d_out, int out_size)
{
    const float* x    = (const float*)d_in[0];
    const float* y    = (const float*)d_in[1];
    const float* z    = (const float*)d_in[2];
    const float* t    = (const float*)d_in[3];
    const float* W0   = (const float*)d_in[4];
    const float* b0   = (const float*)d_in[5];
    const float* Wh   = (const float*)d_in[6];
    const float* bh   = (const float*)d_in[7];
    const float* Wout = (const float*)d_in[8];
    const float* bout = (const float*)d_in[9];
    const float* ac   = (const float*)d_in[10];
    const int N = in_sizes[0];

    pinn_prep<<<(5 * 128 * 128 + 255) / 256, 256>>>(Wh);
    cudaFuncSetAttribute(pinn_mma, cudaFuncAttributeMaxDynamicSharedMemorySize, SMEM_TOTAL);
    pinn_mma<<<N / PTSB, THREADS, SMEM_TOTAL>>>(x, y, z, t, W0, b0, bh, Wout, bout, ac,
                                                (float*)d_out, N);
}

// round 14
// speedup vs baseline: 5.1496x; 1.0363x over previous
#include <cuda_runtime.h>
#include <cuda_fp16.h>
#include <cstdint>

#define PTSB 8
#define THREADS 128

// ACT: 128 rows x 256B (fp16, cols 0..95 used), 16B-chunk XOR swizzle ((row&7)<<4).
#define ACT   0
// Wt (transposed weights, A operand): [m][k] fp16, 256B rows, swizzled. hi + lo.
#define W_H   32768
#define W_L   65536
#define SMEM_TOTAL 98304
#define REDO  49152

__device__ __align__(16) __half g_wt_hi[5 * 128 * 128];
__device__ __align__(16) __half g_wt_lo[5 * 128 * 128];

static __device__ __forceinline__ uint32_t smem_u32(const void* p) {
    uint32_t a;
    asm("{ .reg .u64 t; cvta.to.shared.u64 t, %1; cvt.u32.u64 %0, t; }" : "=r"(a) : "l"(p));
    return a;
}
static __device__ __forceinline__ void ldm_x4(uint32_t* r, uint32_t addr) {
    asm volatile("ldmatrix.sync.aligned.m8n8.x4.shared.b16 {%0,%1,%2,%3}, [%4];"
        : "=r"(r[0]), "=r"(r[1]), "=r"(r[2]), "=r"(r[3]) : "r"(addr));
}
static __device__ __forceinline__ void ldm_x4_t(uint32_t* r, uint32_t addr) {
    asm volatile("ldmatrix.sync.aligned.m8n8.x4.trans.shared.b16 {%0,%1,%2,%3}, [%4];"
        : "=r"(r[0]), "=r"(r[1]), "=r"(r[2]), "=r"(r[3]) : "r"(addr));
}
static __device__ __forceinline__ void mma_f16(float* c, const uint32_t* a, const uint32_t* b) {
    asm volatile("mma.sync.aligned.m16n8k16.row.col.f32.f16.f16.f32 "
        "{%0,%1,%2,%3}, {%4,%5,%6,%7}, {%8,%9}, {%0,%1,%2,%3};"
        : "+f"(c[0]), "+f"(c[1]), "+f"(c[2]), "+f"(c[3])
        : "r"(a[0]), "r"(a[1]), "r"(a[2]), "r"(a[3]), "r"(b[0]), "r"(b[1]));
}
#define CP16(dst, src) asm volatile("cp.async.cg.shared.global [%0], [%1], 16;" :: "r"(dst), "l"(src))
#define CP_COMMIT()    asm volatile("cp.async.commit_group;" ::: "memory")
#define CP_WAIT0()     asm volatile("cp.async.wait_group 0;" ::: "memory")

static __device__ __forceinline__ void fill_w(uint32_t sbase, int l, int wid, int lane) {
    const __half* sh = g_wt_hi + l * 16384 + wid * 32 * 128;
    const __half* sl = g_wt_lo + l * 16384 + wid * 32 * 128;
    #pragma unroll
    for (int it = 0; it < 16; it++) {
        const int c  = lane + 32 * it;
        const int rl = c >> 4, ch = c & 15;
        const uint32_t doff = (uint32_t)(32 * wid + rl) * 256u
                            + ((uint32_t)(ch * 16) ^ (((uint32_t)rl & 7u) << 4));
        const int soff = rl * 128 + ch * 8;
        CP16(sbase + W_H + doff, sh + soff);
        CP16(sbase + W_L + doff, sl + soff);
    }
    CP_COMMIT();
}

__global__ void pinn_prep(const float* __restrict__ Wh) {
    const int i = blockIdx.x * blockDim.x + threadIdx.x;
    if (i < 5 * 128 * 128) {
        const float w = Wh[i];
        const int k = (i >> 7) & 127, m = i & 127;
        const int o = (i & ~16383) + (m << 7) + k;
        const __half h = __float2half(w);
        g_wt_hi[o] = h;
        g_wt_lo[o] = __float2half(w - __half2float(h));
    }
}

__global__ __launch_bounds__(THREADS, 2)
void pinn_mma(const float* __restrict__ x, const float* __restrict__ y,
              const float* __restrict__ z, const float* __restrict__ tt,
              const float* __restrict__ W0, const float* __restrict__ b0,
              const float* __restrict__ bias,
              const float* __restrict__ Wout, const float* __restrict__ bout,
              const float* __restrict__ act_coeff,
              float* __restrict__ out, int N)
{
    extern __shared__ __align__(1024) char sm[];
    const int tid = threadIdx.x, lane = tid & 31, wid = tid >> 5;
    const int arow = lane & 15, hi16 = lane >> 4, g8 = lane >> 2, tg = lane & 3;
    const uint32_t sbase = smem_u32(sm);
    const float ac = __ldg(act_coeff);
    const int PI[6] = {0, 1, 2, 0, 0, 1};
    const int PJ[6] = {0, 1, 2, 1, 2, 2};
    const int g0 = blockIdx.x * PTSB;

    fill_w(sbase, 0, wid, lane);

    // ---------------- layer-0 acts (v-major: col = 8v + p), feature m = tid ----------------
    {
        const int m = tid;
        const float w0j = __ldg(&W0[m]), w1j = __ldg(&W0[128 + m]);
        const float w2j = __ldg(&W0[256 + m]), w3j = __ldg(&W0[384 + m]);
        const float b0j = __ldg(&b0[m]);
        const uint32_t mask = ((uint32_t)m & 7u) << 4;
        const uint32_t rb = (uint32_t)m * 256u;
        #pragma unroll
        for (int p = 0; p < PTSB; p++) {
            const int g = g0 + p;
            const float X0 = __ldg(x + g), X1 = __ldg(y + g), X2 = __ldg(z + g);
            const float X3 = 2.0f * __ldg(tt + g) - 1.0f;
            const float zz = ac * (X0 * w0j + X1 * w1j + X2 * w2j + X3 * w3j + b0j);
            const float a  = tanhf(zz);
            const float t1 = 1.0f - a * a;
            const float dz[4] = {ac * w0j, ac * w1j, ac * w2j, 2.0f * ac * w3j};
            float nv[11];
            nv[0] = a;
            #pragma unroll
            for (int q = 0; q < 4; q++) nv[1 + q] = t1 * dz[q];
            #pragma unroll
            for (int q = 0; q < 6; q++) nv[5 + q] = -2.0f * a * t1 * dz[PI[q]] * dz[PJ[q]];
            #pragma unroll
            for (int v = 0; v < 11; v++) {
                const uint32_t b = 16u * v + 2u * p;
                *(__half*)(sm + ACT + rb + (b ^ mask)) = __float2half(nv[v]);
            }
        }
        #pragma unroll
        for (int c = 88; c < 96; c++) {
            const uint32_t b = 2u * c;
            *(__half*)(sm + ACT + rb + (b ^ mask)) = __float2half(0.0f);
        }
    }
    __syncthreads();

    // hoisted addresses
    uint32_t bb[6];
    const uint32_t bmask = ((uint32_t)arow & 7u) << 4;
    #pragma unroll
    for (int q6 = 0; q6 < 6; q6++) {
        const uint32_t cb = 32u * q6 + 16u * hi16;
        bb[q6] = sbase + ACT + (uint32_t)arow * 256u + (cb ^ bmask);
    }
    uint32_t abase[2];
    #pragma unroll
    for (int j = 0; j < 2; j++)
        abase[j] = sbase + W_H + (uint32_t)(32 * wid + 16 * j + arow) * 256u;
    const uint32_t amask = bmask;

    for (int l = 0; l < 5; l++) {
        CP_WAIT0();

        float acc[2][11][4];
        #pragma unroll
        for (int j = 0; j < 2; j++)
            #pragma unroll
            for (int nt = 0; nt < 11; nt++)
                #pragma unroll
                for (int s = 0; s < 4; s++) acc[j][nt][s] = 0.0f;

        // ---- software-pipelined GEMM: double-buffered fragments ----
        uint32_t wA[2][2][2][4];   // [slot][j][hi/lo][4]
        uint32_t wB[2][6][4];      // [slot][q6][4]
        {
            const uint32_t acol0 = (16u * (uint32_t)hi16) ^ amask;
            #pragma unroll
            for (int j = 0; j < 2; j++) {
                ldm_x4(wA[0][j][0], abase[j] + acol0);
                ldm_x4(wA[0][j][1], abase[j] + acol0 + 32768u);
            }
            #pragma unroll
            for (int q6 = 0; q6 < 6; q6++)
                ldm_x4_t(wB[0][q6], bb[q6]);
        }
        #pragma unroll
        for (int kt = 0; kt < 8; kt++) {
            const int cur = kt & 1, nxt = cur ^ 1;
            if (kt < 7) {
                const uint32_t acol = (32u * (kt + 1) + 16u * (uint32_t)hi16) ^ amask;
                const uint32_t bstep = (uint32_t)(kt + 1) * 4096u;
                #pragma unroll
                for (int j = 0; j < 2; j++) {
                    ldm_x4(wA[nxt][j][0], abase[j] + acol);
                    ldm_x4(wA[nxt][j][1], abase[j] + acol + 32768u);
                }
                #pragma unroll
                for (int q6 = 0; q6 < 6; q6++)
                    ldm_x4_t(wB[nxt][q6], bb[q6] + bstep);
            }
            #pragma unroll
            for (int q6 = 0; q6 < 6; q6++) {
                #pragma unroll
                for (int s = 0; s < 2; s++) {
                    const int nt = 2 * q6 + s;
                    if (nt == 11) continue;
                    #pragma unroll
                    for (int j = 0; j < 2; j++) {
                        float* cc = acc[j][nt];
                        mma_f16(cc, wA[cur][j][0], &wB[cur][q6][2 * s]);
                        mma_f16(cc, wA[cur][j][1], &wB[cur][q6][2 * s]);
                    }
                }
            }
        }
        if (l < 4) fill_w(sbase, l + 1, wid, lane);

        // mix entirely in registers
        float nv[2][11][4];
        #pragma unroll
        for (int j = 0; j < 2; j++) {
            #pragma unroll
            for (int e = 0; e < 4; e++) {
                const int m = 32 * wid + 16 * j + g8 + 8 * (e >> 1);
                const float bz = __ldg(&bias[l * 128 + m]);
                const float a  = tanhf(ac * (acc[j][0][e] + bz));
                const float t1 = 1.0f - a * a;
                float dz[4];
                #pragma unroll
                for (int q = 0; q < 4; q++) dz[q] = ac * acc[j][1 + q][e];
                nv[j][0][e] = a;
                #pragma unroll
                for (int q = 0; q < 4; q++) nv[j][1 + q][e] = t1 * dz[q];
                #pragma unroll
                for (int q = 0; q < 6; q++)
                    nv[j][5 + q][e] = t1 * (ac * acc[j][5 + q][e]
                                            - 2.0f * a * dz[PI[q]] * dz[PJ[q]]);
            }
        }
        __syncthreads();

        const uint32_t mmask = ((uint32_t)g8 & 7u) << 4;
        if (l < 4) {
            #pragma unroll
            for (int j = 0; j < 2; j++) {
                const uint32_t r0 = (uint32_t)(32 * wid + 16 * j + g8) * 256u;
                const uint32_t r1 = r0 + 8u * 256u;
                #pragma unroll
                for (int v = 0; v < 11; v++) {
                    const uint32_t cb = 16u * v + 4u * tg;
                    const __half2 h01 = __halves2half2(__float2half(nv[j][v][0]),
                                                       __float2half(nv[j][v][1]));
                    const __half2 h23 = __halves2half2(__float2half(nv[j][v][2]),
                                                       __float2half(nv[j][v][3]));
                    *(__half2*)(sm + ACT + r0 + (cb ^ mmask)) = h01;
                    *(__half2*)(sm + ACT + r1 + (cb ^ mmask)) = h23;
                }
            }
            __syncthreads();
        } else {
            float* F = (float*)(sm + ACT);
            #pragma unroll
            for (int j = 0; j < 2; j++) {
                const int mr0 = 32 * wid + 16 * j + g8, mr1 = mr0 + 8;
                #pragma unroll
                for (int v = 0; v < 11; v++) {
                    *(float2*)&F[mr0 * 96 + 8 * v + 2 * tg] = make_float2(nv[j][v][0], nv[j][v][1]);
                    *(float2*)&F[mr1 * 96 + 8 * v + 2 * tg] = make_float2(nv[j][v][2], nv[j][v][3]);
                }
            }
            __syncthreads();
        }
    }

    // ---------------- output layer ----------------
    const float* F = (const float*)(sm + ACT);
    float* red = (float*)(sm + REDO);
    for (int c = tid; c < PTSB * 44; c += THREADS) {
        const int p = c / 44, r44 = c % 44, v = r44 >> 2, o = r44 & 3;
        const int col = 8 * v + p;
        float s = 0.0f;
        #pragma unroll 8
        for (int m = 0; m < 128; m++)
            s = fmaf(F[m * 96 + col], __ldg(&Wout[m * 4 + o]), s);
        red[c] = s;
    }
    __syncthreads();

    if (tid < PTSB) {
        const int p = tid, g = g0 + p;
        const float* rd = red + p * 44;
        const float u = rd[0] + __ldg(&bout[0]);
        const float v = rd[1] + __ldg(&bout[1]);
        const float w = rd[2] + __ldg(&bout[2]);
        const float u_x = rd[4],  u_y = rd[8],  u_z = rd[12], u_t = rd[16];
        const float v_x = rd[5],  v_y = rd[9],  v_z = rd[13], v_t = rd[17];
        const float w_x = rd[6],  w_y = rd[10], w_z = rd[14], w_t = rd[18];
        const float p_x = rd[7],  p_y = rd[11], p_z = rd[15];
        const float Hxx_u = rd[20], Hyy_u = rd[24], Hzz_u = rd[28], Hxy_u = rd[32], Hxz_u = rd[36];
        const float Hxx_v = rd[21], Hyy_v = rd[25], Hzz_v = rd[29], Hxy_v = rd[33], Hyz_v = rd[41];
        const float Hxx_w = rd[22], Hyy_w = rd[26], Hzz_w = rd[30], Hxz_w = rd[38], Hyz_w = rd[42];
        const float tau_x = 2.0f * Hxx_u + Hyy_u + Hxy_v + Hzz_u + Hxz_w;
        const float tau_y = Hxy_u + Hxx_v + 2.0f * Hyy_v + Hzz_v + Hyz_w;
        const float tau_z = Hxz_u + Hxx_w + Hyz_v + Hyy_w + 2.0f * Hzz_w;
        out[0 * N + g] = u_x + v_y + w_z;
        out[1 * N + g] = u_t + (u * u_x + v * u_y + w * u_z) + p_x - tau_x;
        out[2 * N + g] = v_t + (u * v_x + v * v_y + w * v_z) + p_y - tau_y;
        out[3 * N + g] = w_t + (u * w_x + v * w_y + w * w_z) + p_z - tau_z + 98.9f;
    }
}

extern "C" void kernel_launch(void* const* d_in, const int* in_sizes, int n_in,
                              void* d_out, int out_size)
{
    const float* x    = (const float*)d_in[0];
    const float* y    = (const float*)d_in[1];
    const float* z    = (const float*)d_in[2];
    const float* t    = (const float*)d_in[3];
    const float* W0   = (const float*)d_in[4];
    const float* b0   = (const float*)d_in[5];
    const float* Wh   = (const float*)d_in[6];
    const float* bh   = (const float*)d_in[7];
    const float* Wout = (const float*)d_in[8];
    const float* bout = (const float*)d_in[9];
    const float* ac   = (const float*)d_in[10];
    const int N = in_sizes[0];

    pinn_prep<<<(5 * 128 * 128 + 255) / 256, 256>>>(Wh);
    cudaFuncSetAttribute(pinn_mma, cudaFuncAttributeMaxDynamicSharedMemorySize, SMEM_TOTAL);
    pinn_mma<<<N / PTSB, THREADS, SMEM_TOTAL>>>(x, y, z, t, W0, b0, bh, Wout, bout, ac,
                                                (float*)d_out, N);
}

// round 15
// speedup vs baseline: 5.8927x; 1.1443x over previous
#include <cuda_runtime.h>
#include <cuda_fp16.h>
#include <cstdint>

#define PTSB 8
#define THREADS 128

// ACT: 128 rows x 256B (fp16, cols 0..95 used), 16B-chunk XOR swizzle ((row&7)<<4).
#define ACT   0
// Wt (transposed weights, A operand): [m][k] fp16, 256B rows, swizzled. hi + lo.
#define W_H   32768
#define W_L   65536
#define SMEM_TOTAL 98304
// after last GEMM the W region is dead: red4 (4 warps x 4 tg x 88) then red (352)
#define RED4  32768
#define REDF  38400

__device__ __align__(16) __half g_wt_hi[5 * 128 * 128];
__device__ __align__(16) __half g_wt_lo[5 * 128 * 128];

static __device__ __forceinline__ uint32_t smem_u32(const void* p) {
    uint32_t a;
    asm("{ .reg .u64 t; cvta.to.shared.u64 t, %1; cvt.u32.u64 %0, t; }" : "=r"(a) : "l"(p));
    return a;
}
static __device__ __forceinline__ void ldm_x4(uint32_t* r, uint32_t addr) {
    asm volatile("ldmatrix.sync.aligned.m8n8.x4.shared.b16 {%0,%1,%2,%3}, [%4];"
        : "=r"(r[0]), "=r"(r[1]), "=r"(r[2]), "=r"(r[3]) : "r"(addr));
}
static __device__ __forceinline__ void ldm_x4_t(uint32_t* r, uint32_t addr) {
    asm volatile("ldmatrix.sync.aligned.m8n8.x4.trans.shared.b16 {%0,%1,%2,%3}, [%4];"
        : "=r"(r[0]), "=r"(r[1]), "=r"(r[2]), "=r"(r[3]) : "r"(addr));
}
static __device__ __forceinline__ void mma_f16(float* c, const uint32_t* a, const uint32_t* b) {
    asm volatile("mma.sync.aligned.m16n8k16.row.col.f32.f16.f16.f32 "
        "{%0,%1,%2,%3}, {%4,%5,%6,%7}, {%8,%9}, {%0,%1,%2,%3};"
        : "+f"(c[0]), "+f"(c[1]), "+f"(c[2]), "+f"(c[3])
        : "r"(a[0]), "r"(a[1]), "r"(a[2]), "r"(a[3]), "r"(b[0]), "r"(b[1]));
}
#define CP16(dst, src) asm volatile("cp.async.cg.shared.global [%0], [%1], 16;" :: "r"(dst), "l"(src))
#define CP_COMMIT()    asm volatile("cp.async.commit_group;" ::: "memory")
#define CP_WAIT0()     asm volatile("cp.async.wait_group 0;" ::: "memory")

static __device__ __forceinline__ void fill_w(uint32_t sbase, int l, int wid, int lane) {
    const __half* sh = g_wt_hi + l * 16384 + wid * 32 * 128;
    const __half* sl = g_wt_lo + l * 16384 + wid * 32 * 128;
    #pragma unroll
    for (int it = 0; it < 16; it++) {
        const int c  = lane + 32 * it;
        const int rl = c >> 4, ch = c & 15;
        const uint32_t doff = (uint32_t)(32 * wid + rl) * 256u
                            + ((uint32_t)(ch * 16) ^ (((uint32_t)rl & 7u) << 4));
        const int soff = rl * 128 + ch * 8;
        CP16(sbase + W_H + doff, sh + soff);
        CP16(sbase + W_L + doff, sl + soff);
    }
    CP_COMMIT();
}

__global__ void pinn_prep(const float* __restrict__ Wh) {
    const int i = blockIdx.x * blockDim.x + threadIdx.x;
    if (i < 5 * 128 * 128) {
        const float w = Wh[i];
        const int k = (i >> 7) & 127, m = i & 127;
        const int o = (i & ~16383) + (m << 7) + k;
        const __half h = __float2half(w);
        g_wt_hi[o] = h;
        g_wt_lo[o] = __float2half(w - __half2float(h));
    }
}

__global__ __launch_bounds__(THREADS, 2)
void pinn_mma(const float* __restrict__ x, const float* __restrict__ y,
              const float* __restrict__ z, const float* __restrict__ tt,
              const float* __restrict__ W0, const float* __restrict__ b0,
              const float* __restrict__ bias,
              const float* __restrict__ Wout, const float* __restrict__ bout,
              const float* __restrict__ act_coeff,
              float* __restrict__ out, int N)
{
    extern __shared__ __align__(1024) char sm[];
    const int tid = threadIdx.x, lane = tid & 31, wid = tid >> 5;
    const int arow = lane & 15, hi16 = lane >> 4, g8 = lane >> 2, tg = lane & 3;
    const uint32_t sbase = smem_u32(sm);
    const float ac = __ldg(act_coeff);
    const int PI[6] = {0, 1, 2, 0, 0, 1};
    const int PJ[6] = {0, 1, 2, 1, 2, 2};
    const int g0 = blockIdx.x * PTSB;

    fill_w(sbase, 0, wid, lane);

    // ---------------- layer-0 acts (v-major: col = 8v + p), feature m = tid ----------------
    {
        const int m = tid;
        const float w0j = __ldg(&W0[m]), w1j = __ldg(&W0[128 + m]);
        const float w2j = __ldg(&W0[256 + m]), w3j = __ldg(&W0[384 + m]);
        const float b0j = __ldg(&b0[m]);
        const uint32_t mask = ((uint32_t)m & 7u) << 4;
        const uint32_t rb = (uint32_t)m * 256u;
        #pragma unroll
        for (int p = 0; p < PTSB; p++) {
            const int g = g0 + p;
            const float X0 = __ldg(x + g), X1 = __ldg(y + g), X2 = __ldg(z + g);
            const float X3 = 2.0f * __ldg(tt + g) - 1.0f;
            const float zz = ac * (X0 * w0j + X1 * w1j + X2 * w2j + X3 * w3j + b0j);
            const float a  = tanhf(zz);
            const float t1 = 1.0f - a * a;
            const float dz[4] = {ac * w0j, ac * w1j, ac * w2j, 2.0f * ac * w3j};
            float nv[11];
            nv[0] = a;
            #pragma unroll
            for (int q = 0; q < 4; q++) nv[1 + q] = t1 * dz[q];
            #pragma unroll
            for (int q = 0; q < 6; q++) nv[5 + q] = -2.0f * a * t1 * dz[PI[q]] * dz[PJ[q]];
            #pragma unroll
            for (int v = 0; v < 11; v++) {
                const uint32_t b = 16u * v + 2u * p;
                *(__half*)(sm + ACT + rb + (b ^ mask)) = __float2half(nv[v]);
            }
        }
        #pragma unroll
        for (int c = 88; c < 96; c++) {
            const uint32_t b = 2u * c;
            *(__half*)(sm + ACT + rb + (b ^ mask)) = __float2half(0.0f);
        }
    }
    __syncthreads();

    // hoisted addresses
    uint32_t bb[6];
    const uint32_t bmask = ((uint32_t)arow & 7u) << 4;
    #pragma unroll
    for (int q6 = 0; q6 < 6; q6++) {
        const uint32_t cb = 32u * q6 + 16u * hi16;
        bb[q6] = sbase + ACT + (uint32_t)arow * 256u + (cb ^ bmask);
    }
    uint32_t abase[2];
    #pragma unroll
    for (int j = 0; j < 2; j++)
        abase[j] = sbase + W_H + (uint32_t)(32 * wid + 16 * j + arow) * 256u;
    const uint32_t amask = bmask;

    for (int l = 0; l < 5; l++) {
        CP_WAIT0();

        float acc[2][11][4];
        #pragma unroll
        for (int j = 0; j < 2; j++)
            #pragma unroll
            for (int nt = 0; nt < 11; nt++)
                #pragma unroll
                for (int s = 0; s < 4; s++) acc[j][nt][s] = 0.0f;

        // ---- software-pipelined GEMM: double-buffered fragments ----
        uint32_t wA[2][2][2][4];
        uint32_t wB[2][6][4];
        {
            const uint32_t acol0 = (16u * (uint32_t)hi16) ^ amask;
            #pragma unroll
            for (int j = 0; j < 2; j++) {
                ldm_x4(wA[0][j][0], abase[j] + acol0);
                ldm_x4(wA[0][j][1], abase[j] + acol0 + 32768u);
            }
            #pragma unroll
            for (int q6 = 0; q6 < 6; q6++)
                ldm_x4_t(wB[0][q6], bb[q6]);
        }
        #pragma unroll
        for (int kt = 0; kt < 8; kt++) {
            const int cur = kt & 1, nxt = cur ^ 1;
            if (kt < 7) {
                const uint32_t acol = (32u * (kt + 1) + 16u * (uint32_t)hi16) ^ amask;
                const uint32_t bstep = (uint32_t)(kt + 1) * 4096u;
                #pragma unroll
                for (int j = 0; j < 2; j++) {
                    ldm_x4(wA[nxt][j][0], abase[j] + acol);
                    ldm_x4(wA[nxt][j][1], abase[j] + acol + 32768u);
                }
                #pragma unroll
                for (int q6 = 0; q6 < 6; q6++)
                    ldm_x4_t(wB[nxt][q6], bb[q6] + bstep);
            }
            #pragma unroll
            for (int q6 = 0; q6 < 6; q6++) {
                #pragma unroll
                for (int s = 0; s < 2; s++) {
                    const int nt = 2 * q6 + s;
                    if (nt == 11) continue;
                    #pragma unroll
                    for (int j = 0; j < 2; j++) {
                        float* cc = acc[j][nt];
                        mma_f16(cc, wA[cur][j][0], &wB[cur][q6][2 * s]);
                        mma_f16(cc, wA[cur][j][1], &wB[cur][q6][2 * s]);
                    }
                }
            }
        }
        if (l < 4) {
            fill_w(sbase, l + 1, wid, lane);

            // mix in registers, store acts
            float nv[2][11][4];
            #pragma unroll
            for (int j = 0; j < 2; j++) {
                #pragma unroll
                for (int e = 0; e < 4; e++) {
                    const int m = 32 * wid + 16 * j + g8 + 8 * (e >> 1);
                    const float bz = __ldg(&bias[l * 128 + m]);
                    const float a  = tanhf(ac * (acc[j][0][e] + bz));
                    const float t1 = 1.0f - a * a;
                    float dz[4];
                    #pragma unroll
                    for (int q = 0; q < 4; q++) dz[q] = ac * acc[j][1 + q][e];
                    nv[j][0][e] = a;
                    #pragma unroll
                    for (int q = 0; q < 4; q++) nv[j][1 + q][e] = t1 * dz[q];
                    #pragma unroll
                    for (int q = 0; q < 6; q++)
                        nv[j][5 + q][e] = t1 * (ac * acc[j][5 + q][e]
                                                - 2.0f * a * dz[PI[q]] * dz[PJ[q]]);
                }
            }
            __syncthreads();   // all warps' B reads of acts complete

            const uint32_t mmask = ((uint32_t)g8 & 7u) << 4;
            #pragma unroll
            for (int j = 0; j < 2; j++) {
                const uint32_t r0 = (uint32_t)(32 * wid + 16 * j + g8) * 256u;
                const uint32_t r1 = r0 + 8u * 256u;
                #pragma unroll
                for (int v = 0; v < 11; v++) {
                    const uint32_t cb = 16u * v + 4u * tg;
                    const __half2 h01 = __halves2half2(__float2half(nv[j][v][0]),
                                                       __float2half(nv[j][v][1]));
                    const __half2 h23 = __halves2half2(__float2half(nv[j][v][2]),
                                                       __float2half(nv[j][v][3]));
                    *(__half2*)(sm + ACT + r0 + (cb ^ mmask)) = h01;
                    *(__half2*)(sm + ACT + r1 + (cb ^ mmask)) = h23;
                }
            }
            __syncthreads();
        } else {
            // ---- l=4: fold Wout in registers; no act stores, no F region ----
            float part[88];   // [sc][v*4+o]
            #pragma unroll
            for (int k = 0; k < 88; k++) part[k] = 0.0f;
            float w4[2][2][4];
            #pragma unroll
            for (int j = 0; j < 2; j++)
                #pragma unroll
                for (int rh = 0; rh < 2; rh++) {
                    const int m = 32 * wid + 16 * j + g8 + 8 * rh;
                    #pragma unroll
                    for (int o = 0; o < 4; o++) w4[j][rh][o] = __ldg(&Wout[m * 4 + o]);
                }
            #pragma unroll
            for (int j = 0; j < 2; j++) {
                #pragma unroll
                for (int e = 0; e < 4; e++) {
                    const int rh = e >> 1, sc = e & 1;
                    const int m = 32 * wid + 16 * j + g8 + 8 * rh;
                    const float bz = __ldg(&bias[4 * 128 + m]);
                    const float a  = tanhf(ac * (acc[j][0][e] + bz));
                    const float t1 = 1.0f - a * a;
                    float dz[4];
                    #pragma unroll
                    for (int q = 0; q < 4; q++) dz[q] = ac * acc[j][1 + q][e];
                    float nvv[11];
                    nvv[0] = a;
                    #pragma unroll
                    for (int q = 0; q < 4; q++) nvv[1 + q] = t1 * dz[q];
                    #pragma unroll
                    for (int q = 0; q < 6; q++)
                        nvv[5 + q] = t1 * (ac * acc[j][5 + q][e]
                                           - 2.0f * a * dz[PI[q]] * dz[PJ[q]]);
                    #pragma unroll
                    for (int v = 0; v < 11; v++)
                        #pragma unroll
                        for (int o = 0; o < 4; o++)
                            part[sc * 44 + v * 4 + o] =
                                fmaf(w4[j][rh][o], nvv[v], part[sc * 44 + v * 4 + o]);
                }
            }
            __syncthreads();   // W region (RED4) now safe to overwrite

            // reduce over g8 (lane bits 2..4)
            #pragma unroll
            for (int k = 0; k < 88; k++) {
                float s = part[k];
                s += __shfl_xor_sync(0xffffffffu, s, 4);
                s += __shfl_xor_sync(0xffffffffu, s, 8);
                s += __shfl_xor_sync(0xffffffffu, s, 16);
                part[k] = s;
            }
            if (g8 == 0) {   // lanes 0..3
                float* r4 = (float*)(sm + RED4) + (wid * 4 + tg) * 88;
                #pragma unroll
                for (int k = 0; k < 88; k++) r4[k] = part[k];
            }
            __syncthreads();
        }
    }

    // final cross-warp sum: 8 pts x 44
    float* red = (float*)(sm + REDF);
    {
        const float* r4 = (const float*)(sm + RED4);
        for (int c = tid; c < PTSB * 44; c += THREADS) {
            const int p = c / 44, k = c % 44;
            const int tgp = p >> 1, scp = p & 1;
            float s = 0.0f;
            #pragma unroll
            for (int w = 0; w < 4; w++)
                s += r4[(w * 4 + tgp) * 88 + scp * 44 + k];
            red[c] = s;
        }
    }
    __syncthreads();

    if (tid < PTSB) {
        const int p = tid, g = g0 + p;
        const float* rd = red + p * 44;
        const float u = rd[0] + __ldg(&bout[0]);
        const float v = rd[1] + __ldg(&bout[1]);
        const float w = rd[2] + __ldg(&bout[2]);
        const float u_x = rd[4],  u_y = rd[8],  u_z = rd[12], u_t = rd[16];
        const float v_x = rd[5],  v_y = rd[9],  v_z = rd[13], v_t = rd[17];
        const float w_x = rd[6],  w_y = rd[10], w_z = rd[14], w_t = rd[18];
        const float p_x = rd[7],  p_y = rd[11], p_z = rd[15];
        const float Hxx_u = rd[20], Hyy_u = rd[24], Hzz_u = rd[28], Hxy_u = rd[32], Hxz_u = rd[36];
        const float Hxx_v = rd[21], Hyy_v = rd[25], Hzz_v = rd[29], Hxy_v = rd[33], Hyz_v = rd[41];
        const float Hxx_w = rd[22], Hyy_w = rd[26], Hzz_w = rd[30], Hxz_w = rd[38], Hyz_w = rd[42];
        const float tau_x = 2.0f * Hxx_u + Hyy_u + Hxy_v + Hzz_u + Hxz_w;
        const float tau_y = Hxy_u + Hxx_v + 2.0f * Hyy_v + Hzz_v + Hyz_w;
        const float tau_z = Hxz_u + Hxx_w + Hyz_v + Hyy_w + 2.0f * Hzz_w;
        out[0 * N + g] = u_x + v_y + w_z;
        out[1 * N + g] = u_t + (u * u_x + v * u_y + w * u_z) + p_x - tau_x;
        out[2 * N + g] = v_t + (u * v_x + v * v_y + w * v_z) + p_y - tau_y;
        out[3 * N + g] = w_t + (u * w_x + v * w_y + w * w_z) + p_z - tau_z + 98.9f;
    }
}

extern "C" void kernel_launch(void* const* d_in, const int* in_sizes, int n_in,
                              void* d_out, int out_size)
{
    const float* x    = (const float*)d_in[0];
    const float* y    = (const float*)d_in[1];
    const float* z    = (const float*)d_in[2];
    const float* t    = (const float*)d_in[3];
    const float* W0   = (const float*)d_in[4];
    const float* b0   = (const float*)d_in[5];
    const float* Wh   = (const float*)d_in[6];
    const float* bh   = (const float*)d_in[7];
    const float* Wout = (const float*)d_in[8];
    const float* bout = (const float*)d_in[9];
    const float* ac   = (const float*)d_in[10];
    const int N = in_sizes[0];

    pinn_prep<<<(5 * 128 * 128 + 255) / 256, 256>>>(Wh);
    cudaFuncSetAttribute(pinn_mma, cudaFuncAttributeMaxDynamicSharedMemorySize, SMEM_TOTAL);
    pinn_mma<<<N / PTSB, THREADS, SMEM_TOTAL>>>(x, y, z, t, W0, b0, bh, Wout, bout, ac,
                                                (float*)d_out, N);
}

// round 16
// speedup vs baseline: 5.9217x; 1.0049x over previous
#include <cuda_runtime.h>
#include <cuda_fp16.h>
#include <cstdint>

#define PTSB 8
#define THREADS 128

// ACT: 128 rows x 256B (fp16, cols 0..95 used), 16B-chunk XOR swizzle ((row&7)<<4).
#define ACT   0
// Wt (transposed weights, A operand): [m][k] fp16, 256B rows, swizzled. hi + lo.
#define W_H   32768
#define W_L   65536
#define SMEM_TOTAL 98304
// after last GEMM the W region is dead: red4 (4 warps x 4 tg x 88) then red (352)
#define RED4  32768
#define REDF  38400

__device__ __align__(16) __half g_wt_hi[5 * 128 * 128];
__device__ __align__(16) __half g_wt_lo[5 * 128 * 128];

static __device__ __forceinline__ uint32_t smem_u32(const void* p) {
    uint32_t a;
    asm("{ .reg .u64 t; cvta.to.shared.u64 t, %1; cvt.u32.u64 %0, t; }" : "=r"(a) : "l"(p));
    return a;
}
// tanh(x) = 1 - 2/(exp2(2*log2e*x)+1); ex2/rcp approx rel err ~2^-22 -> abs err ~1e-7,
// far below the fp16 act-rounding already in the error budget. Branch-free, saturates right.
static __device__ __forceinline__ float fast_tanh(float xx) {
    float e;
    asm("ex2.approx.f32 %0, %1;" : "=f"(e) : "f"(xx * 2.8853900817779268f));
    float r;
    asm("rcp.approx.f32 %0, %1;" : "=f"(r) : "f"(e + 1.0f));
    return fmaf(-2.0f, r, 1.0f);
}
static __device__ __forceinline__ void ldm_x4(uint32_t* r, uint32_t addr) {
    asm volatile("ldmatrix.sync.aligned.m8n8.x4.shared.b16 {%0,%1,%2,%3}, [%4];"
        : "=r"(r[0]), "=r"(r[1]), "=r"(r[2]), "=r"(r[3]) : "r"(addr));
}
static __device__ __forceinline__ void ldm_x4_t(uint32_t* r, uint32_t addr) {
    asm volatile("ldmatrix.sync.aligned.m8n8.x4.trans.shared.b16 {%0,%1,%2,%3}, [%4];"
        : "=r"(r[0]), "=r"(r[1]), "=r"(r[2]), "=r"(r[3]) : "r"(addr));
}
static __device__ __forceinline__ void mma_f16(float* c, const uint32_t* a, const uint32_t* b) {
    asm volatile("mma.sync.aligned.m16n8k16.row.col.f32.f16.f16.f32 "
        "{%0,%1,%2,%3}, {%4,%5,%6,%7}, {%8,%9}, {%0,%1,%2,%3};"
        : "+f"(c[0]), "+f"(c[1]), "+f"(c[2]), "+f"(c[3])
        : "r"(a[0]), "r"(a[1]), "r"(a[2]), "r"(a[3]), "r"(b[0]), "r"(b[1]));
}
#define CP16(dst, src) asm volatile("cp.async.cg.shared.global [%0], [%1], 16;" :: "r"(dst), "l"(src))
#define CP_COMMIT()    asm volatile("cp.async.commit_group;" ::: "memory")
#define CP_WAIT0()     asm volatile("cp.async.wait_group 0;" ::: "memory")

static __device__ __forceinline__ void fill_w(uint32_t sbase, int l, int wid, int lane) {
    const __half* sh = g_wt_hi + l * 16384 + wid * 32 * 128;
    const __half* sl = g_wt_lo + l * 16384 + wid * 32 * 128;
    #pragma unroll
    for (int it = 0; it < 16; it++) {
        const int c  = lane + 32 * it;
        const int rl = c >> 4, ch = c & 15;
        const uint32_t doff = (uint32_t)(32 * wid + rl) * 256u
                            + ((uint32_t)(ch * 16) ^ (((uint32_t)rl & 7u) << 4));
        const int soff = rl * 128 + ch * 8;
        CP16(sbase + W_H + doff, sh + soff);
        CP16(sbase + W_L + doff, sl + soff);
    }
    CP_COMMIT();
}

__global__ void pinn_prep(const float* __restrict__ Wh) {
    const int i = blockIdx.x * blockDim.x + threadIdx.x;
    if (i < 5 * 128 * 128) {
        const float w = Wh[i];
        const int k = (i >> 7) & 127, m = i & 127;
        const int o = (i & ~16383) + (m << 7) + k;
        const __half h = __float2half(w);
        g_wt_hi[o] = h;
        g_wt_lo[o] = __float2half(w - __half2float(h));
    }
}

__global__ __launch_bounds__(THREADS, 2)
void pinn_mma(const float* __restrict__ x, const float* __restrict__ y,
              const float* __restrict__ z, const float* __restrict__ tt,
              const float* __restrict__ W0, const float* __restrict__ b0,
              const float* __restrict__ bias,
              const float* __restrict__ Wout, const float* __restrict__ bout,
              const float* __restrict__ act_coeff,
              float* __restrict__ out, int N)
{
    extern __shared__ __align__(1024) char sm[];
    const int tid = threadIdx.x, lane = tid & 31, wid = tid >> 5;
    const int arow = lane & 15, hi16 = lane >> 4, g8 = lane >> 2, tg = lane & 3;
    const uint32_t sbase = smem_u32(sm);
    const float ac = __ldg(act_coeff);
    const int PI[6] = {0, 1, 2, 0, 0, 1};
    const int PJ[6] = {0, 1, 2, 1, 2, 2};
    const int g0 = blockIdx.x * PTSB;

    fill_w(sbase, 0, wid, lane);

    // ---------------- layer-0 acts (v-major: col = 8v + p), feature m = tid ----------------
    {
        const int m = tid;
        const float w0j = __ldg(&W0[m]), w1j = __ldg(&W0[128 + m]);
        const float w2j = __ldg(&W0[256 + m]), w3j = __ldg(&W0[384 + m]);
        const float b0j = __ldg(&b0[m]);
        const uint32_t mask = ((uint32_t)m & 7u) << 4;
        const uint32_t rb = (uint32_t)m * 256u;
        #pragma unroll
        for (int p = 0; p < PTSB; p++) {
            const int g = g0 + p;
            const float X0 = __ldg(x + g), X1 = __ldg(y + g), X2 = __ldg(z + g);
            const float X3 = 2.0f * __ldg(tt + g) - 1.0f;
            const float zz = ac * (X0 * w0j + X1 * w1j + X2 * w2j + X3 * w3j + b0j);
            const float a  = fast_tanh(zz);
            const float t1 = 1.0f - a * a;
            const float dz[4] = {ac * w0j, ac * w1j, ac * w2j, 2.0f * ac * w3j};
            float nv[11];
            nv[0] = a;
            #pragma unroll
            for (int q = 0; q < 4; q++) nv[1 + q] = t1 * dz[q];
            #pragma unroll
            for (int q = 0; q < 6; q++) nv[5 + q] = -2.0f * a * t1 * dz[PI[q]] * dz[PJ[q]];
            #pragma unroll
            for (int v = 0; v < 11; v++) {
                const uint32_t b = 16u * v + 2u * p;
                *(__half*)(sm + ACT + rb + (b ^ mask)) = __float2half(nv[v]);
            }
        }
        #pragma unroll
        for (int c = 88; c < 96; c++) {
            const uint32_t b = 2u * c;
            *(__half*)(sm + ACT + rb + (b ^ mask)) = __float2half(0.0f);
        }
    }
    __syncthreads();

    // hoisted addresses
    uint32_t bb[6];
    const uint32_t bmask = ((uint32_t)arow & 7u) << 4;
    #pragma unroll
    for (int q6 = 0; q6 < 6; q6++) {
        const uint32_t cb = 32u * q6 + 16u * hi16;
        bb[q6] = sbase + ACT + (uint32_t)arow * 256u + (cb ^ bmask);
    }
    uint32_t abase[2];
    #pragma unroll
    for (int j = 0; j < 2; j++)
        abase[j] = sbase + W_H + (uint32_t)(32 * wid + 16 * j + arow) * 256u;
    const uint32_t amask = bmask;

    for (int l = 0; l < 5; l++) {
        CP_WAIT0();

        float acc[2][11][4];
        #pragma unroll
        for (int j = 0; j < 2; j++)
            #pragma unroll
            for (int nt = 0; nt < 11; nt++)
                #pragma unroll
                for (int s = 0; s < 4; s++) acc[j][nt][s] = 0.0f;

        // ---- software-pipelined GEMM: double-buffered fragments ----
        uint32_t wA[2][2][2][4];
        uint32_t wB[2][6][4];
        {
            const uint32_t acol0 = (16u * (uint32_t)hi16) ^ amask;
            #pragma unroll
            for (int j = 0; j < 2; j++) {
                ldm_x4(wA[0][j][0], abase[j] + acol0);
                ldm_x4(wA[0][j][1], abase[j] + acol0 + 32768u);
            }
            #pragma unroll
            for (int q6 = 0; q6 < 6; q6++)
                ldm_x4_t(wB[0][q6], bb[q6]);
        }
        #pragma unroll
        for (int kt = 0; kt < 8; kt++) {
            const int cur = kt & 1, nxt = cur ^ 1;
            if (kt < 7) {
                const uint32_t acol = (32u * (kt + 1) + 16u * (uint32_t)hi16) ^ amask;
                const uint32_t bstep = (uint32_t)(kt + 1) * 4096u;
                #pragma unroll
                for (int j = 0; j < 2; j++) {
                    ldm_x4(wA[nxt][j][0], abase[j] + acol);
                    ldm_x4(wA[nxt][j][1], abase[j] + acol + 32768u);
                }
                #pragma unroll
                for (int q6 = 0; q6 < 6; q6++)
                    ldm_x4_t(wB[nxt][q6], bb[q6] + bstep);
            }
            #pragma unroll
            for (int q6 = 0; q6 < 6; q6++) {
                #pragma unroll
                for (int s = 0; s < 2; s++) {
                    const int nt = 2 * q6 + s;
                    if (nt == 11) continue;
                    #pragma unroll
                    for (int j = 0; j < 2; j++) {
                        float* cc = acc[j][nt];
                        mma_f16(cc, wA[cur][j][0], &wB[cur][q6][2 * s]);
                        mma_f16(cc, wA[cur][j][1], &wB[cur][q6][2 * s]);
                    }
                }
            }
        }
        if (l < 4) {
            fill_w(sbase, l + 1, wid, lane);

            // mix in registers, store acts
            float nv[2][11][4];
            #pragma unroll
            for (int j = 0; j < 2; j++) {
                #pragma unroll
                for (int e = 0; e < 4; e++) {
                    const int m = 32 * wid + 16 * j + g8 + 8 * (e >> 1);
                    const float bz = __ldg(&bias[l * 128 + m]);
                    const float a  = fast_tanh(ac * (acc[j][0][e] + bz));
                    const float t1 = 1.0f - a * a;
                    float dz[4];
                    #pragma unroll
                    for (int q = 0; q < 4; q++) dz[q] = ac * acc[j][1 + q][e];
                    nv[j][0][e] = a;
                    #pragma unroll
                    for (int q = 0; q < 4; q++) nv[j][1 + q][e] = t1 * dz[q];
                    #pragma unroll
                    for (int q = 0; q < 6; q++)
                        nv[j][5 + q][e] = t1 * (ac * acc[j][5 + q][e]
                                                - 2.0f * a * dz[PI[q]] * dz[PJ[q]]);
                }
            }
            __syncthreads();   // all warps' B reads of acts complete

            const uint32_t mmask = ((uint32_t)g8 & 7u) << 4;
            #pragma unroll
            for (int j = 0; j < 2; j++) {
                const uint32_t r0 = (uint32_t)(32 * wid + 16 * j + g8) * 256u;
                const uint32_t r1 = r0 + 8u * 256u;
                #pragma unroll
                for (int v = 0; v < 11; v++) {
                    const uint32_t cb = 16u * v + 4u * tg;
                    const __half2 h01 = __halves2half2(__float2half(nv[j][v][0]),
                                                       __float2half(nv[j][v][1]));
                    const __half2 h23 = __halves2half2(__float2half(nv[j][v][2]),
                                                       __float2half(nv[j][v][3]));
                    *(__half2*)(sm + ACT + r0 + (cb ^ mmask)) = h01;
                    *(__half2*)(sm + ACT + r1 + (cb ^ mmask)) = h23;
                }
            }
            __syncthreads();
        } else {
            // ---- l=4: fold Wout in registers; no act stores, no F region ----
            float part[88];   // [sc][v*4+o]
            #pragma unroll
            for (int k = 0; k < 88; k++) part[k] = 0.0f;
            float w4[2][2][4];
            #pragma unroll
            for (int j = 0; j < 2; j++)
                #pragma unroll
                for (int rh = 0; rh < 2; rh++) {
                    const int m = 32 * wid + 16 * j + g8 + 8 * rh;
                    #pragma unroll
                    for (int o = 0; o < 4; o++) w4[j][rh][o] = __ldg(&Wout[m * 4 + o]);
                }
            #pragma unroll
            for (int j = 0; j < 2; j++) {
                #pragma unroll
                for (int e = 0; e < 4; e++) {
                    const int rh = e >> 1, sc = e & 1;
                    const int m = 32 * wid + 16 * j + g8 + 8 * rh;
                    const float bz = __ldg(&bias[4 * 128 + m]);
                    const float a  = fast_tanh(ac * (acc[j][0][e] + bz));
                    const float t1 = 1.0f - a * a;
                    float dz[4];
                    #pragma unroll
                    for (int q = 0; q < 4; q++) dz[q] = ac * acc[j][1 + q][e];
                    float nvv[11];
                    nvv[0] = a;
                    #pragma unroll
                    for (int q = 0; q < 4; q++) nvv[1 + q] = t1 * dz[q];
                    #pragma unroll
                    for (int q = 0; q < 6; q++)
                        nvv[5 + q] = t1 * (ac * acc[j][5 + q][e]
                                           - 2.0f * a * dz[PI[q]] * dz[PJ[q]]);
                    #pragma unroll
                    for (int v = 0; v < 11; v++)
                        #pragma unroll
                        for (int o = 0; o < 4; o++)
                            part[sc * 44 + v * 4 + o] =
                                fmaf(w4[j][rh][o], nvv[v], part[sc * 44 + v * 4 + o]);
                }
            }
            __syncthreads();   // W region (RED4) now safe to overwrite

            // reduce over g8 (lane bits 2..4)
            #pragma unroll
            for (int k = 0; k < 88; k++) {
                float s = part[k];
                s += __shfl_xor_sync(0xffffffffu, s, 4);
                s += __shfl_xor_sync(0xffffffffu, s, 8);
                s += __shfl_xor_sync(0xffffffffu, s, 16);
                part[k] = s;
            }
            if (g8 == 0) {   // lanes 0..3
                float* r4 = (float*)(sm + RED4) + (wid * 4 + tg) * 88;
                #pragma unroll
                for (int k = 0; k < 88; k++) r4[k] = part[k];
            }
            __syncthreads();
        }
    }

    // final cross-warp sum: 8 pts x 44
    float* red = (float*)(sm + REDF);
    {
        const float* r4 = (const float*)(sm + RED4);
        for (int c = tid; c < PTSB * 44; c += THREADS) {
            const int p = c / 44, k = c % 44;
            const int tgp = p >> 1, scp = p & 1;
            float s = 0.0f;
            #pragma unroll
            for (int w = 0; w < 4; w++)
                s += r4[(w * 4 + tgp) * 88 + scp * 44 + k];
            red[c] = s;
        }
    }
    __syncthreads();

    if (tid < PTSB) {
        const int p = tid, g = g0 + p;
        const float* rd = red + p * 44;
        const float u = rd[0] + __ldg(&bout[0]);
        const float v = rd[1] + __ldg(&bout[1]);
        const float w = rd[2] + __ldg(&bout[2]);
        const float u_x = rd[4],  u_y = rd[8],  u_z = rd[12], u_t = rd[16];
        const float v_x = rd[5],  v_y = rd[9],  v_z = rd[13], v_t = rd[17];
        const float w_x = rd[6],  w_y = rd[10], w_z = rd[14], w_t = rd[18];
        const float p_x = rd[7],  p_y = rd[11], p_z = rd[15];
        const float Hxx_u = rd[20], Hyy_u = rd[24], Hzz_u = rd[28], Hxy_u = rd[32], Hxz_u = rd[36];
        const float Hxx_v = rd[21], Hyy_v = rd[25], Hzz_v = rd[29], Hxy_v = rd[33], Hyz_v = rd[41];
        const float Hxx_w = rd[22], Hyy_w = rd[26], Hzz_w = rd[30], Hxz_w = rd[38], Hyz_w = rd[42];
        const float tau_x = 2.0f * Hxx_u + Hyy_u + Hxy_v + Hzz_u + Hxz_w;
        const float tau_y = Hxy_u + Hxx_v + 2.0f * Hyy_v + Hzz_v + Hyz_w;
        const float tau_z = Hxz_u + Hxx_w + Hyz_v + Hyy_w + 2.0f * Hzz_w;
        out[0 * N + g] = u_x + v_y + w_z;
        out[1 * N + g] = u_t + (u * u_x + v * u_y + w * u_z) + p_x - tau_x;
        out[2 * N + g] = v_t + (u * v_x + v * v_y + w * v_z) + p_y - tau_y;
        out[3 * N + g] = w_t + (u * w_x + v * w_y + w * w_z) + p_z - tau_z + 98.9f;
    }
}

extern "C" void kernel_launch(void* const* d_in, const int* in_sizes, int n_in,
                              void* d_out, int out_size)
{
    const float* x    = (const float*)d_in[0];
    const float* y    = (const float*)d_in[1];
    const float* z    = (const float*)d_in[2];
    const float* t    = (const float*)d_in[3];
    const float* W0   = (const float*)d_in[4];
    const float* b0   = (const float*)d_in[5];
    const float* Wh   = (const float*)d_in[6];
    const float* bh   = (const float*)d_in[7];
    const float* Wout = (const float*)d_in[8];
    const float* bout = (const float*)d_in[9];
    const float* ac   = (const float*)d_in[10];
    const int N = in_sizes[0];

    pinn_prep<<<(5 * 128 * 128 + 255) / 256, 256>>>(Wh);
    cudaFuncSetAttribute(pinn_mma, cudaFuncAttributeMaxDynamicSharedMemorySize, SMEM_TOTAL);
    pinn_mma<<<N / PTSB, THREADS, SMEM_TOTAL>>>(x, y, z, t, W0, b0, bh, Wout, bout, ac,
                                                (float*)d_out, N);
}